// round 7
// baseline (speedup 1.0000x reference)
#include <cuda_runtime.h>
#include <math.h>
#include <stdint.h>

#define BB 8
#define DD 256
#define NN 2048
#define NH 4
#define HD 64
#define QTILE 128
#define KTILE 64

typedef unsigned long long u64;
typedef unsigned int u32;

// Scratch. g_q/g_k TRANSPOSED per-head [b][h][tok][dd]; g_v/g_x natural [b][ch][tok].
__device__ float g_q[BB*DD*NN];
__device__ float g_k[BB*DD*NN];
__device__ float g_v[BB*DD*NN];
__device__ float g_x[BB*DD*NN];

// ---------------- packed f32x2 helpers ----------------
__device__ __forceinline__ void ffma2(u64& d, u64 a, u64 b) {
    asm("fma.rn.f32x2 %0, %1, %2, %3;" : "=l"(d) : "l"(a), "l"(b), "l"(d));
}
__device__ __forceinline__ u64 bcast2(float x) {
    u64 r; asm("mov.b64 %0, {%1, %1};" : "=l"(r) : "f"(x)); return r;
}
__device__ __forceinline__ float2 unpk(u64 v) {
    float lo, hi; asm("mov.b64 {%0, %1}, %2;" : "=f"(lo), "=f"(hi) : "l"(v));
    return make_float2(lo, hi);
}
__device__ __forceinline__ u32 f2tf32(float x) {
    u32 r; asm("cvt.rna.tf32.f32 %0, %1;" : "=r"(r) : "f"(x)); return r;
}
__device__ __forceinline__ u32 smem_u32(const void* p) {
    u32 a; asm("{ .reg .u64 t; cvta.to.shared.u64 t, %1; cvt.u32.u64 %0, t; }" : "=r"(a) : "l"(p));
    return a;
}
__device__ __forceinline__ void mma_tf32(float c[4], u32 a0, u32 a1, u32 a2, u32 a3,
                                         u32 b0, u32 b1) {
    asm volatile("mma.sync.aligned.m16n8k8.row.col.f32.tf32.tf32.f32 "
        "{%0,%1,%2,%3}, {%4,%5,%6,%7}, {%8,%9}, {%0,%1,%2,%3};"
        : "+f"(c[0]), "+f"(c[1]), "+f"(c[2]), "+f"(c[3])
        : "r"(a0), "r"(a1), "r"(a2), "r"(a3), "r"(b0), "r"(b1));
}
#define LDSM4(r, a) asm volatile( \
    "ldmatrix.sync.aligned.m8n8.x4.shared.b16 {%0,%1,%2,%3}, [%4];" \
    : "=r"((r)[0]), "=r"((r)[1]), "=r"((r)[2]), "=r"((r)[3]) : "r"(a))
#define LDSM2(r0, r1, a) asm volatile( \
    "ldmatrix.sync.aligned.m8n8.x2.shared.b16 {%0,%1}, [%2];" \
    : "=r"(r0), "=r"(r1) : "r"(a))
#define STS4(a, x, y, z, w_) asm volatile( \
    "st.shared.v4.b32 [%0], {%1,%2,%3,%4};" :: "r"(a), "r"(x), "r"(y), "r"(z), "r"(w_) : "memory")
#define STS2(a, x, y) asm volatile( \
    "st.shared.v2.b32 [%0], {%1,%2};" :: "r"(a), "r"(x), "r"(y) : "memory")

// ---------------------------------------------------------------------------
// Projection GEMM (fp32 exact, f32x2, o-pair packed). 64o x 128n tile, 256 thr.
// TRANS=1 writes per-head transposed [b][h][tok][dd].
// ---------------------------------------------------------------------------
template <int TRANS>
__global__ __launch_bounds__(256) void proj_kernel(
    const float* __restrict__ W, const float* __restrict__ bias,
    const float* __restrict__ X, float* __restrict__ Y)
{
    __shared__ float sW[16*68];
    __shared__ float sX[16*132];

    const int b  = blockIdx.z;
    const int o0 = blockIdx.y * 64;
    const int n0 = blockIdx.x * 128;
    const int t  = threadIdx.x;
    const int tx = t & 31;
    const int ty = t >> 5;

    const float* Xb = X + (size_t)b * DD * NN;
    u64 acc2[4][4];
#pragma unroll
    for (int i = 0; i < 4; i++)
#pragma unroll
        for (int j = 0; j < 4; j++) acc2[i][j] = 0ull;

    for (int k0 = 0; k0 < DD; k0 += 16) {
#pragma unroll
        for (int i = 0; i < 4; i++) {
            int idx = t + i * 256;
            int oo = idx >> 4, kk = idx & 15;
            sW[kk * 68 + oo] = W[(o0 + oo) * DD + k0 + kk];
        }
#pragma unroll
        for (int i = 0; i < 2; i++) {
            int idx4 = t + i * 256;
            int kk = idx4 >> 5, c4 = idx4 & 31;
            *(float4*)&sX[kk * 132 + c4 * 4] =
                *(const float4*)&Xb[(k0 + kk) * NN + n0 + c4 * 4];
        }
        __syncthreads();
#pragma unroll
        for (int kk = 0; kk < 16; kk++) {
            const ulonglong2 w01 = *(const ulonglong2*)&sW[kk * 68 + ty * 8];
            const ulonglong2 w23 = *(const ulonglong2*)&sW[kk * 68 + ty * 8 + 4];
            const float4 xv = *(const float4*)&sX[kk * 132 + tx * 4];
            u64 x0 = bcast2(xv.x), x1 = bcast2(xv.y), x2 = bcast2(xv.z), x3 = bcast2(xv.w);
            ffma2(acc2[0][0], w01.x, x0); ffma2(acc2[0][1], w01.x, x1);
            ffma2(acc2[0][2], w01.x, x2); ffma2(acc2[0][3], w01.x, x3);
            ffma2(acc2[1][0], w01.y, x0); ffma2(acc2[1][1], w01.y, x1);
            ffma2(acc2[1][2], w01.y, x2); ffma2(acc2[1][3], w01.y, x3);
            ffma2(acc2[2][0], w23.x, x0); ffma2(acc2[2][1], w23.x, x1);
            ffma2(acc2[2][2], w23.x, x2); ffma2(acc2[2][3], w23.x, x3);
            ffma2(acc2[3][0], w23.y, x0); ffma2(acc2[3][1], w23.y, x1);
            ffma2(acc2[3][2], w23.y, x2); ffma2(acc2[3][3], w23.y, x3);
        }
        __syncthreads();
    }

    float v[8][4];
#pragma unroll
    for (int op = 0; op < 4; op++)
#pragma unroll
        for (int n = 0; n < 4; n++) {
            float2 p = unpk(acc2[op][n]);
            v[op * 2][n] = p.x;
            v[op * 2 + 1][n] = p.y;
        }
#pragma unroll
    for (int oi = 0; oi < 8; oi++) {
        int o = o0 + ty * 8 + oi;
        float bv = bias[o];
        if (TRANS) {
            int dd = o >> 2, hh = o & 3;
            float* base = Y + (((size_t)b * NH + hh) * NN + n0 + tx * 4) * HD + dd;
#pragma unroll
            for (int n = 0; n < 4; n++) base[n * HD] = v[oi][n] + bv;
        } else {
            float* Yb = Y + (size_t)b * DD * NN;
            *(float4*)&Yb[o * NN + n0 + tx * 4] = make_float4(
                v[oi][0] + bv, v[oi][1] + bv, v[oi][2] + bv, v[oi][3] + bv);
        }
    }
}

// ---------------------------------------------------------------------------
// mma.sync tf32 flash attention: Q frags in registers, S in nb-pairs (ks-outer).
// CTA = (b, h, 128-query tile), 128 threads (4 warps), warp owns 32 q rows.
// SMEM: sK[64][64](tok,dd), sV[64][64](dd,tok), sP[128][64] (also Q staging).
// Row = 64 u32 = 256 B = 16 chunks of 16 B; chunk' = chunk ^ (row & 7).
// ---------------------------------------------------------------------------
__global__ __launch_bounds__(128, 3) void attn_mma(const int* __restrict__ mask)
{
    extern __shared__ u32 smu[];
    const u32 sbase = smem_u32(smu);
    const u32 Ko = 0;
    const u32 Vo = 4096 * 4;
    const u32 Po = 8192 * 4;
    int* skm = (int*)(smu + 8192 + 8192);

    const int t = threadIdx.x;
    const int w = t >> 5, lane = t & 31;
    const int gid = lane >> 2, tig = lane & 3;
    const int b = blockIdx.z, h = blockIdx.y;
    const int q0 = blockIdx.x * QTILE;

    // ldmatrix address components
    const int arow0 = w * 32 + (lane & 15);   // A rows (mi adds 16)
    const int ahi = lane >> 4;                // chunk +1 for col+4 matrices
    const int brow = lane & 7;                // B rows within nb block
    const int bhi = (lane >> 3) & 1;

    // ---- stage Q into sP region (fold 1/8, tf32, swizzled), then frags->regs ----
    const float* qb = g_q + (((size_t)b * NH + h) * NN + q0) * HD;
#pragma unroll
    for (int i = 0; i < 16; i++) {
        int idx = t + i * 128;
        int row = idx >> 4, c = idx & 15;
        float4 v = *(const float4*)(qb + row * HD + c * 4);
        u32 a = sbase + Po + row * 256 + ((c ^ (row & 7)) << 4);
        STS4(a, f2tf32(v.x * 0.125f), f2tf32(v.y * 0.125f),
                f2tf32(v.z * 0.125f), f2tf32(v.w * 0.125f));
    }
    __syncthreads();
    u32 qf[2][8][4];
#pragma unroll
    for (int mi = 0; mi < 2; mi++)
#pragma unroll
        for (int ks = 0; ks < 8; ks++) {
            int r = arow0 + mi * 16;
            u32 a = sbase + Po + r * 256 + (((ks * 2 + ahi) ^ (r & 7)) << 4);
            LDSM4(qf[mi][ks], a);
        }

    const int* mb_ = mask + (size_t)b * NN;
    int qm[4];
#pragma unroll
    for (int mi = 0; mi < 2; mi++) {
        qm[2 * mi]     = mb_[q0 + w * 32 + mi * 16 + gid];
        qm[2 * mi + 1] = mb_[q0 + w * 32 + mi * 16 + gid + 8];
    }

    float oc[2][8][4];
#pragma unroll
    for (int mi = 0; mi < 2; mi++)
#pragma unroll
        for (int nb = 0; nb < 8; nb++)
#pragma unroll
            for (int e = 0; e < 4; e++) oc[mi][nb][e] = 0.f;
    float lsum[4] = {0.f, 0.f, 0.f, 0.f};

    const float* kb0 = g_k + (((size_t)b * NH + h) * NN) * HD;
    const float* vb0 = g_v + ((size_t)b * DD + h) * NN;

    for (int k0 = 0; k0 < NN; k0 += KTILE) {
        __syncthreads();   // prev-iter reads of sK/sV/sP done
        // ---- K fill: [tok][dd] ----
#pragma unroll
        for (int i = 0; i < 8; i++) {
            int idx = t + i * 128;
            int row = idx >> 4, c = idx & 15;
            float4 v = *(const float4*)(kb0 + (size_t)(k0 + row) * HD + c * 4);
            u32 a = sbase + Ko + row * 256 + ((c ^ (row & 7)) << 4);
            STS4(a, f2tf32(v.x), f2tf32(v.y), f2tf32(v.z), f2tf32(v.w));
        }
        // ---- V fill: [dd][tok] ----
#pragma unroll
        for (int i = 0; i < 8; i++) {
            int idx = t + i * 128;
            int dd = idx >> 4, c = idx & 15;
            float4 v = *(const float4*)(vb0 + (size_t)dd * (NH * NN) + k0 + c * 4);
            u32 a = sbase + Vo + dd * 256 + ((c ^ (dd & 7)) << 4);
            STS4(a, f2tf32(v.x), f2tf32(v.y), f2tf32(v.z), f2tf32(v.w));
        }
        if (t < KTILE) skm[t] = mb_[k0 + t];
        __syncthreads();

        // ---- S + softmax, nb-pairs, ks-outer (4 independent mma chains) ----
#pragma unroll
        for (int half = 0; half < 4; half++) {
            float sc[2][2][4];
#pragma unroll
            for (int mi = 0; mi < 2; mi++)
#pragma unroll
                for (int p = 0; p < 2; p++)
#pragma unroll
                    for (int e = 0; e < 4; e++) sc[mi][p][e] = 0.f;
#pragma unroll
            for (int ks = 0; ks < 8; ks++) {
#pragma unroll
                for (int p = 0; p < 2; p++) {
                    int nb = half * 2 + p;
                    int r = nb * 8 + brow;
                    u32 a = sbase + Ko + r * 256 + (((ks * 2 + bhi) ^ (r & 7)) << 4);
                    u32 B0, B1; LDSM2(B0, B1, a);
                    mma_tf32(sc[0][p], qf[0][ks][0], qf[0][ks][1], qf[0][ks][2], qf[0][ks][3], B0, B1);
                    mma_tf32(sc[1][p], qf[1][ks][0], qf[1][ks][1], qf[1][ks][2], qf[1][ks][3], B0, B1);
                }
            }
#pragma unroll
            for (int p = 0; p < 2; p++) {
                int nb = half * 2 + p;
                int col0 = nb * 8 + tig * 2;
                int km0 = skm[col0], km1 = skm[col0 + 1];
                float e0 = (qm[0] && km0) ? __expf(sc[0][p][0]) : 0.f;
                float e1 = (qm[0] && km1) ? __expf(sc[0][p][1]) : 0.f;
                float e2 = (qm[1] && km0) ? __expf(sc[0][p][2]) : 0.f;
                float e3 = (qm[1] && km1) ? __expf(sc[0][p][3]) : 0.f;
                float f0 = (qm[2] && km0) ? __expf(sc[1][p][0]) : 0.f;
                float f1 = (qm[2] && km1) ? __expf(sc[1][p][1]) : 0.f;
                float f2 = (qm[3] && km0) ? __expf(sc[1][p][2]) : 0.f;
                float f3 = (qm[3] && km1) ? __expf(sc[1][p][3]) : 0.f;
                lsum[0] += e0 + e1; lsum[1] += e2 + e3;
                lsum[2] += f0 + f1; lsum[3] += f2 + f3;
                int ch = col0 >> 2;
                int r0 = w * 32 + gid;
                u32 a0 = sbase + Po + r0 * 256 + ((ch ^ (r0 & 7)) << 4) + (tig & 1) * 8;
                STS2(a0, f2tf32(e0), f2tf32(e1));
                int r1 = r0 + 8;
                u32 a1 = sbase + Po + r1 * 256 + ((ch ^ (r1 & 7)) << 4) + (tig & 1) * 8;
                STS2(a1, f2tf32(e2), f2tf32(e3));
                int r2 = r0 + 16;
                u32 a2 = sbase + Po + r2 * 256 + ((ch ^ (r2 & 7)) << 4) + (tig & 1) * 8;
                STS2(a2, f2tf32(f0), f2tf32(f1));
                int r3 = r0 + 24;
                u32 a3 = sbase + Po + r3 * 256 + ((ch ^ (r3 & 7)) << 4) + (tig & 1) * 8;
                STS2(a3, f2tf32(f2), f2tf32(f3));
            }
        }
        __syncwarp();

        // ---- O += P V (kt-outer, 16 independent chains) ----
#pragma unroll
        for (int kt = 0; kt < 8; kt++) {
            u32 A0[4], A1[4];
            {
                int r = arow0;
                u32 a = sbase + Po + r * 256 + (((kt * 2 + ahi) ^ (r & 7)) << 4);
                LDSM4(A0, a);
                r = arow0 + 16;
                a = sbase + Po + r * 256 + (((kt * 2 + ahi) ^ (r & 7)) << 4);
                LDSM4(A1, a);
            }
#pragma unroll
            for (int nb = 0; nb < 8; nb++) {
                int r = nb * 8 + brow;
                u32 a = sbase + Vo + r * 256 + (((kt * 2 + bhi) ^ (r & 7)) << 4);
                u32 B0, B1; LDSM2(B0, B1, a);
                mma_tf32(oc[0][nb], A0[0], A0[1], A0[2], A0[3], B0, B1);
                mma_tf32(oc[1][nb], A1[0], A1[1], A1[2], A1[3], B0, B1);
            }
        }
    }

    // ---- epilogue ----
#pragma unroll
    for (int i = 0; i < 4; i++) {
        lsum[i] += __shfl_xor_sync(~0u, lsum[i], 1);
        lsum[i] += __shfl_xor_sync(~0u, lsum[i], 2);
    }
    float inv[4];
#pragma unroll
    for (int i = 0; i < 4; i++) inv[i] = 1.f / lsum[i];

    float* xb = g_x + ((size_t)b * DD + h) * NN;
#pragma unroll
    for (int mi = 0; mi < 2; mi++) {
        int r0 = q0 + w * 32 + mi * 16 + gid;
        int r1 = r0 + 8;
#pragma unroll
        for (int nb = 0; nb < 8; nb++) {
            int dd0 = nb * 8 + tig * 2;
            xb[(size_t)dd0 * (NH * NN) + r0]       = oc[mi][nb][0] * inv[2*mi];
            xb[(size_t)(dd0 + 1) * (NH * NN) + r0] = oc[mi][nb][1] * inv[2*mi];
            xb[(size_t)dd0 * (NH * NN) + r1]       = oc[mi][nb][2] * inv[2*mi+1];
            xb[(size_t)(dd0 + 1) * (NH * NN) + r1] = oc[mi][nb][3] * inv[2*mi+1];
        }
    }
}

// ---------------------------------------------------------------------------
extern "C" void kernel_launch(void* const* d_in, const int* in_sizes, int n_in,
                              void* d_out, int out_size)
{
    const float* query = (const float*)d_in[0];
    const float* key_  = (const float*)d_in[1];
    const float* value = (const float*)d_in[2];
    const int*   mask  = (const int*)  d_in[3];
    const float* Wq = (const float*)d_in[4];
    const float* bq = (const float*)d_in[5];
    const float* Wk = (const float*)d_in[6];
    const float* bk = (const float*)d_in[7];
    const float* Wv = (const float*)d_in[8];
    const float* bv = (const float*)d_in[9];
    const float* Wm = (const float*)d_in[10];
    const float* bm = (const float*)d_in[11];
    float* out = (float*)d_out;

    float *q, *k, *v, *x;
    cudaGetSymbolAddress((void**)&q, g_q);
    cudaGetSymbolAddress((void**)&k, g_k);
    cudaGetSymbolAddress((void**)&v, g_v);
    cudaGetSymbolAddress((void**)&x, g_x);

    dim3 pgrid(NN / 128, DD / 64, BB);
    proj_kernel<1><<<pgrid, 256>>>(Wq, bq, query, q);
    proj_kernel<1><<<pgrid, 256>>>(Wk, bk, key_,  k);
    proj_kernel<0><<<pgrid, 256>>>(Wv, bv, value, v);

    const int asmem = (4096 + 4096 + 8192) * 4 + 64 * 4;  // 65792
    cudaFuncSetAttribute(attn_mma, cudaFuncAttributeMaxDynamicSharedMemorySize, asmem);
    dim3 agrid(NN / QTILE, NH, BB);
    attn_mma<<<agrid, 128, asmem>>>(mask);

    proj_kernel<0><<<pgrid, 256>>>(Wm, bm, x, out);
}

// round 8
// speedup vs baseline: 1.8429x; 1.8429x over previous
#include <cuda_runtime.h>
#include <math.h>
#include <stdint.h>

#define BB 8
#define DD 256
#define NN 2048
#define NH 4
#define HD 64
#define QTILE 128
#define KTILE 64

typedef unsigned long long u64;
typedef unsigned int u32;

// Scratch. g_q/g_k TRANSPOSED per-head [b][h][tok][dd]; g_v/g_x natural [b][ch][tok].
__device__ float g_q[BB*DD*NN];
__device__ float g_k[BB*DD*NN];
__device__ float g_v[BB*DD*NN];
__device__ float g_x[BB*DD*NN];

// ---------------- packed f32x2 helpers ----------------
__device__ __forceinline__ void ffma2(u64& d, u64 a, u64 b) {
    asm("fma.rn.f32x2 %0, %1, %2, %3;" : "=l"(d) : "l"(a), "l"(b), "l"(d));
}
__device__ __forceinline__ u64 bcast2(float x) {
    u64 r; asm("mov.b64 %0, {%1, %1};" : "=l"(r) : "f"(x)); return r;
}
__device__ __forceinline__ float2 unpk(u64 v) {
    float lo, hi; asm("mov.b64 {%0, %1}, %2;" : "=f"(lo), "=f"(hi) : "l"(v));
    return make_float2(lo, hi);
}
__device__ __forceinline__ u32 f2tf32(float x) {
    u32 r; asm("cvt.rna.tf32.f32 %0, %1;" : "=r"(r) : "f"(x)); return r;
}
__device__ __forceinline__ u32 smem_u32(const void* p) {
    u32 a; asm("{ .reg .u64 t; cvta.to.shared.u64 t, %1; cvt.u32.u64 %0, t; }" : "=r"(a) : "l"(p));
    return a;
}
__device__ __forceinline__ void mma_tf32(float c[4], u32 a0, u32 a1, u32 a2, u32 a3,
                                         u32 b0, u32 b1) {
    asm volatile("mma.sync.aligned.m16n8k8.row.col.f32.tf32.tf32.f32 "
        "{%0,%1,%2,%3}, {%4,%5,%6,%7}, {%8,%9}, {%0,%1,%2,%3};"
        : "+f"(c[0]), "+f"(c[1]), "+f"(c[2]), "+f"(c[3])
        : "r"(a0), "r"(a1), "r"(a2), "r"(a3), "r"(b0), "r"(b1));
}
#define LDSM4(r, a) asm volatile( \
    "ldmatrix.sync.aligned.m8n8.x4.shared.b16 {%0,%1,%2,%3}, [%4];" \
    : "=r"((r)[0]), "=r"((r)[1]), "=r"((r)[2]), "=r"((r)[3]) : "r"(a))
#define LDSM2(r0, r1, a) asm volatile( \
    "ldmatrix.sync.aligned.m8n8.x2.shared.b16 {%0,%1}, [%2];" \
    : "=r"(r0), "=r"(r1) : "r"(a))
#define STS4(a, x, y, z, w_) asm volatile( \
    "st.shared.v4.b32 [%0], {%1,%2,%3,%4};" :: "r"(a), "r"(x), "r"(y), "r"(z), "r"(w_) : "memory")
#define STS2(a, x, y) asm volatile( \
    "st.shared.v2.b32 [%0], {%1,%2};" :: "r"(a), "r"(x), "r"(y) : "memory")

// ---------------------------------------------------------------------------
// Projection GEMM (fp32 exact, f32x2, o-pair packed). 64o x 128n tile, 256 thr.
// TRANS=1 writes per-head transposed [b][h][tok][dd].
// ---------------------------------------------------------------------------
template <int TRANS>
__global__ __launch_bounds__(256) void proj_kernel(
    const float* __restrict__ W, const float* __restrict__ bias,
    const float* __restrict__ X, float* __restrict__ Y)
{
    __shared__ float sW[16*68];
    __shared__ float sX[16*132];

    const int b  = blockIdx.z;
    const int o0 = blockIdx.y * 64;
    const int n0 = blockIdx.x * 128;
    const int t  = threadIdx.x;
    const int tx = t & 31;
    const int ty = t >> 5;

    const float* Xb = X + (size_t)b * DD * NN;
    u64 acc2[4][4];
#pragma unroll
    for (int i = 0; i < 4; i++)
#pragma unroll
        for (int j = 0; j < 4; j++) acc2[i][j] = 0ull;

    for (int k0 = 0; k0 < DD; k0 += 16) {
#pragma unroll
        for (int i = 0; i < 4; i++) {
            int idx = t + i * 256;
            int oo = idx >> 4, kk = idx & 15;
            sW[kk * 68 + oo] = W[(o0 + oo) * DD + k0 + kk];
        }
#pragma unroll
        for (int i = 0; i < 2; i++) {
            int idx4 = t + i * 256;
            int kk = idx4 >> 5, c4 = idx4 & 31;
            *(float4*)&sX[kk * 132 + c4 * 4] =
                *(const float4*)&Xb[(k0 + kk) * NN + n0 + c4 * 4];
        }
        __syncthreads();
#pragma unroll
        for (int kk = 0; kk < 16; kk++) {
            const ulonglong2 w01 = *(const ulonglong2*)&sW[kk * 68 + ty * 8];
            const ulonglong2 w23 = *(const ulonglong2*)&sW[kk * 68 + ty * 8 + 4];
            const float4 xv = *(const float4*)&sX[kk * 132 + tx * 4];
            u64 x0 = bcast2(xv.x), x1 = bcast2(xv.y), x2 = bcast2(xv.z), x3 = bcast2(xv.w);
            ffma2(acc2[0][0], w01.x, x0); ffma2(acc2[0][1], w01.x, x1);
            ffma2(acc2[0][2], w01.x, x2); ffma2(acc2[0][3], w01.x, x3);
            ffma2(acc2[1][0], w01.y, x0); ffma2(acc2[1][1], w01.y, x1);
            ffma2(acc2[1][2], w01.y, x2); ffma2(acc2[1][3], w01.y, x3);
            ffma2(acc2[2][0], w23.x, x0); ffma2(acc2[2][1], w23.x, x1);
            ffma2(acc2[2][2], w23.x, x2); ffma2(acc2[2][3], w23.x, x3);
            ffma2(acc2[3][0], w23.y, x0); ffma2(acc2[3][1], w23.y, x1);
            ffma2(acc2[3][2], w23.y, x2); ffma2(acc2[3][3], w23.y, x3);
        }
        __syncthreads();
    }

    float v[8][4];
#pragma unroll
    for (int op = 0; op < 4; op++)
#pragma unroll
        for (int n = 0; n < 4; n++) {
            float2 p = unpk(acc2[op][n]);
            v[op * 2][n] = p.x;
            v[op * 2 + 1][n] = p.y;
        }
#pragma unroll
    for (int oi = 0; oi < 8; oi++) {
        int o = o0 + ty * 8 + oi;
        float bv = bias[o];
        if (TRANS) {
            int dd = o >> 2, hh = o & 3;
            float* base = Y + (((size_t)b * NH + hh) * NN + n0 + tx * 4) * HD + dd;
#pragma unroll
            for (int n = 0; n < 4; n++) base[n * HD] = v[oi][n] + bv;
        } else {
            float* Yb = Y + (size_t)b * DD * NN;
            *(float4*)&Yb[o * NN + n0 + tx * 4] = make_float4(
                v[oi][0] + bv, v[oi][1] + bv, v[oi][2] + bv, v[oi][3] + bv);
        }
    }
}

// ---------------------------------------------------------------------------
// mma.sync tf32 flash attention. CTA = (b, h, 128-q tile), 256 threads,
// 8 warps as 4(m: 32 q rows) x 2(n: 32 cols). ldmatrix + swizzled tiles.
// SMEM: sQ[128][64], sK[64][64](tok,dd), sV[64][64](dd,tok), sP[128][64].
// Row = 64 u32 = 256 B = 16 chunks of 16 B; chunk' = chunk ^ (row & 7).
// ---------------------------------------------------------------------------
__global__ __launch_bounds__(256, 2) void attn_mma(const int* __restrict__ mask)
{
    extern __shared__ u32 smu[];
    const u32 sbase = smem_u32(smu);
    const u32 Qo = 0;
    const u32 Ko = 32768;
    const u32 Vo = 49152;
    const u32 Po = 65536;
    int* skm = (int*)(smu + 24576);          // 64 ints
    float* sL = (float*)(smu + 24640);       // [2][128]

    const int t = threadIdx.x;
    const int w = t >> 5, lane = t & 31;
    const int wm = w >> 1, wn = w & 1;
    const int gid = lane >> 2, tig = lane & 3;
    const int b = blockIdx.z, h = blockIdx.y;
    const int q0 = blockIdx.x * QTILE;

    // ldmatrix address components
    const int arow0 = wm * 32 + (lane & 15);  // A rows (mi adds 16)
    const int ahi = lane >> 4;                // chunk +1 for col+4 matrices
    const int brow = lane & 7;                // B rows within nb block
    const int bhi = (lane >> 3) & 1;

    // ---- Q fill (fold 1/8, tf32, swizzled) ----
    const float* qb = g_q + (((size_t)b * NH + h) * NN + q0) * HD;
#pragma unroll
    for (int i = 0; i < 8; i++) {
        int idx = t + i * 256;
        int row = idx >> 4, c = idx & 15;
        float4 v = *(const float4*)(qb + row * HD + c * 4);
        u32 a = sbase + Qo + row * 256 + ((c ^ (row & 7)) << 4);
        STS4(a, f2tf32(v.x * 0.125f), f2tf32(v.y * 0.125f),
                f2tf32(v.z * 0.125f), f2tf32(v.w * 0.125f));
    }

    const int* mb_ = mask + (size_t)b * NN;
    int qm[4];
    qm[0] = mb_[q0 + wm * 32 + gid];
    qm[1] = mb_[q0 + wm * 32 + gid + 8];
    qm[2] = mb_[q0 + wm * 32 + gid + 16];
    qm[3] = mb_[q0 + wm * 32 + gid + 24];

    float oc[2][4][4];
#pragma unroll
    for (int mi = 0; mi < 2; mi++)
#pragma unroll
        for (int nb = 0; nb < 4; nb++)
#pragma unroll
            for (int e = 0; e < 4; e++) oc[mi][nb][e] = 0.f;
    float lsum[4] = {0.f, 0.f, 0.f, 0.f};

    const float* kb0 = g_k + (((size_t)b * NH + h) * NN) * HD;
    const float* vb0 = g_v + ((size_t)b * DD + h) * NN;

    for (int k0 = 0; k0 < NN; k0 += KTILE) {
        __syncthreads();   // prev-iter PV reads of sK/sV/sP done; Q fill visible
        // ---- K fill: [tok][dd] ----
#pragma unroll
        for (int i = 0; i < 4; i++) {
            int idx = t + i * 256;
            int row = idx >> 4, c = idx & 15;
            float4 v = *(const float4*)(kb0 + (size_t)(k0 + row) * HD + c * 4);
            u32 a = sbase + Ko + row * 256 + ((c ^ (row & 7)) << 4);
            STS4(a, f2tf32(v.x), f2tf32(v.y), f2tf32(v.z), f2tf32(v.w));
        }
        // ---- V fill: [dd][tok] ----
#pragma unroll
        for (int i = 0; i < 4; i++) {
            int idx = t + i * 256;
            int dd = idx >> 4, c = idx & 15;
            float4 v = *(const float4*)(vb0 + (size_t)dd * (NH * NN) + k0 + c * 4);
            u32 a = sbase + Vo + dd * 256 + ((c ^ (dd & 7)) << 4);
            STS4(a, f2tf32(v.x), f2tf32(v.y), f2tf32(v.z), f2tf32(v.w));
        }
        if (t < KTILE) skm[t] = mb_[k0 + t];
        __syncthreads();

        // ---- S = Q K^T (warp block: 32 q x 32 k; 8 independent chains) ----
        float sc[2][4][4];
#pragma unroll
        for (int mi = 0; mi < 2; mi++)
#pragma unroll
            for (int nb = 0; nb < 4; nb++)
#pragma unroll
                for (int e = 0; e < 4; e++) sc[mi][nb][e] = 0.f;
#pragma unroll
        for (int ks = 0; ks < 8; ks++) {
            u32 A0[4], A1[4];
            {
                int r = arow0;
                u32 a = sbase + Qo + r * 256 + (((ks * 2 + ahi) ^ (r & 7)) << 4);
                LDSM4(A0, a);
                r = arow0 + 16;
                a = sbase + Qo + r * 256 + (((ks * 2 + ahi) ^ (r & 7)) << 4);
                LDSM4(A1, a);
            }
#pragma unroll
            for (int nb = 0; nb < 4; nb++) {
                int rr = wn * 32 + nb * 8 + brow;
                u32 ab = sbase + Ko + rr * 256 + (((ks * 2 + bhi) ^ (rr & 7)) << 4);
                u32 B0, B1; LDSM2(B0, B1, ab);
                mma_tf32(sc[0][nb], A0[0], A0[1], A0[2], A0[3], B0, B1);
                mma_tf32(sc[1][nb], A1[0], A1[1], A1[2], A1[3], B0, B1);
            }
        }

        // ---- softmax (no-max), P -> sP ----
#pragma unroll
        for (int nb = 0; nb < 4; nb++) {
            int col0 = wn * 32 + nb * 8 + tig * 2;
            int km0 = skm[col0], km1 = skm[col0 + 1];
            float e0 = (qm[0] && km0) ? __expf(sc[0][nb][0]) : 0.f;
            float e1 = (qm[0] && km1) ? __expf(sc[0][nb][1]) : 0.f;
            float e2 = (qm[1] && km0) ? __expf(sc[0][nb][2]) : 0.f;
            float e3 = (qm[1] && km1) ? __expf(sc[0][nb][3]) : 0.f;
            float f0 = (qm[2] && km0) ? __expf(sc[1][nb][0]) : 0.f;
            float f1 = (qm[2] && km1) ? __expf(sc[1][nb][1]) : 0.f;
            float f2 = (qm[3] && km0) ? __expf(sc[1][nb][2]) : 0.f;
            float f3 = (qm[3] && km1) ? __expf(sc[1][nb][3]) : 0.f;
            lsum[0] += e0 + e1; lsum[1] += e2 + e3;
            lsum[2] += f0 + f1; lsum[3] += f2 + f3;
            int ch = col0 >> 2;
            int r0 = wm * 32 + gid;
            u32 a0 = sbase + Po + r0 * 256 + ((ch ^ (r0 & 7)) << 4) + (tig & 1) * 8;
            STS2(a0, f2tf32(e0), f2tf32(e1));
            int r1 = r0 + 8;
            u32 a1 = sbase + Po + r1 * 256 + ((ch ^ (r1 & 7)) << 4) + (tig & 1) * 8;
            STS2(a1, f2tf32(e2), f2tf32(e3));
            int r2 = r0 + 16;
            u32 a2 = sbase + Po + r2 * 256 + ((ch ^ (r2 & 7)) << 4) + (tig & 1) * 8;
            STS2(a2, f2tf32(f0), f2tf32(f1));
            int r3 = r0 + 24;
            u32 a3 = sbase + Po + r3 * 256 + ((ch ^ (r3 & 7)) << 4) + (tig & 1) * 8;
            STS2(a3, f2tf32(f2), f2tf32(f3));
        }
        __syncthreads();   // P visible to both n-warps

        // ---- O += P V (kt-outer, 8 independent chains) ----
#pragma unroll
        for (int kt = 0; kt < 8; kt++) {
            u32 A0[4], A1[4];
            {
                int r = arow0;
                u32 a = sbase + Po + r * 256 + (((kt * 2 + ahi) ^ (r & 7)) << 4);
                LDSM4(A0, a);
                r = arow0 + 16;
                a = sbase + Po + r * 256 + (((kt * 2 + ahi) ^ (r & 7)) << 4);
                LDSM4(A1, a);
            }
#pragma unroll
            for (int nb = 0; nb < 4; nb++) {
                int rr = wn * 32 + nb * 8 + brow;
                u32 ab = sbase + Vo + rr * 256 + (((kt * 2 + bhi) ^ (rr & 7)) << 4);
                u32 B0, B1; LDSM2(B0, B1, ab);
                mma_tf32(oc[0][nb], A0[0], A0[1], A0[2], A0[3], B0, B1);
                mma_tf32(oc[1][nb], A1[0], A1[1], A1[2], A1[3], B0, B1);
            }
        }
    }

    // ---- reduce l across tig lanes, then across n-warps via smem ----
#pragma unroll
    for (int i = 0; i < 4; i++) {
        lsum[i] += __shfl_xor_sync(~0u, lsum[i], 1);
        lsum[i] += __shfl_xor_sync(~0u, lsum[i], 2);
    }
    if (tig == 0) {
        sL[wn * 128 + wm * 32 + gid]      = lsum[0];
        sL[wn * 128 + wm * 32 + gid + 8]  = lsum[1];
        sL[wn * 128 + wm * 32 + gid + 16] = lsum[2];
        sL[wn * 128 + wm * 32 + gid + 24] = lsum[3];
    }
    __syncthreads();
    float inv[4];
#pragma unroll
    for (int i = 0; i < 4; i++) {
        int rl = wm * 32 + ((i & 1) ? 8 : 0) + ((i >> 1) ? 16 : 0) + gid;
        inv[i] = 1.f / (sL[rl] + sL[128 + rl]);
    }

    // ---- epilogue ----
    float* xb = g_x + ((size_t)b * DD + h) * NN;
#pragma unroll
    for (int mi = 0; mi < 2; mi++) {
        int r0 = q0 + wm * 32 + mi * 16 + gid;
        int r1 = r0 + 8;
#pragma unroll
        for (int nb = 0; nb < 4; nb++) {
            int dd0 = wn * 32 + nb * 8 + tig * 2;
            xb[(size_t)dd0 * (NH * NN) + r0]       = oc[mi][nb][0] * inv[2*mi];
            xb[(size_t)(dd0 + 1) * (NH * NN) + r0] = oc[mi][nb][1] * inv[2*mi];
            xb[(size_t)dd0 * (NH * NN) + r1]       = oc[mi][nb][2] * inv[2*mi+1];
            xb[(size_t)(dd0 + 1) * (NH * NN) + r1] = oc[mi][nb][3] * inv[2*mi+1];
        }
    }
}

// ---------------------------------------------------------------------------
extern "C" void kernel_launch(void* const* d_in, const int* in_sizes, int n_in,
                              void* d_out, int out_size)
{
    const float* query = (const float*)d_in[0];
    const float* key_  = (const float*)d_in[1];
    const float* value = (const float*)d_in[2];
    const int*   mask  = (const int*)  d_in[3];
    const float* Wq = (const float*)d_in[4];
    const float* bq = (const float*)d_in[5];
    const float* Wk = (const float*)d_in[6];
    const float* bk = (const float*)d_in[7];
    const float* Wv = (const float*)d_in[8];
    const float* bv = (const float*)d_in[9];
    const float* Wm = (const float*)d_in[10];
    const float* bm = (const float*)d_in[11];
    float* out = (float*)d_out;

    float *q, *k, *v, *x;
    cudaGetSymbolAddress((void**)&q, g_q);
    cudaGetSymbolAddress((void**)&k, g_k);
    cudaGetSymbolAddress((void**)&v, g_v);
    cudaGetSymbolAddress((void**)&x, g_x);

    dim3 pgrid(NN / 128, DD / 64, BB);
    proj_kernel<1><<<pgrid, 256>>>(Wq, bq, query, q);
    proj_kernel<1><<<pgrid, 256>>>(Wk, bk, key_,  k);
    proj_kernel<0><<<pgrid, 256>>>(Wv, bv, value, v);

    const int asmem = 98304 + 64 * 4 + 2 * 128 * 4;  // 99584
    cudaFuncSetAttribute(attn_mma, cudaFuncAttributeMaxDynamicSharedMemorySize, asmem);
    dim3 agrid(NN / QTILE, NH, BB);
    attn_mma<<<agrid, 256, asmem>>>(mask);

    proj_kernel<0><<<pgrid, 256>>>(Wm, bm, x, out);
}

// round 9
// speedup vs baseline: 1.9974x; 1.0838x over previous
#include <cuda_runtime.h>
#include <math.h>
#include <stdint.h>

#define BB 8
#define DD 256
#define NN 2048
#define NH 4
#define HD 64
#define QTILE 128
#define KTILE 64

typedef unsigned long long u64;
typedef unsigned int u32;

// Scratch. g_q/g_k TRANSPOSED per-head [b][h][tok][dd] (tf32 bits, q pre-scaled);
// g_v natural [b][ch][tok] (tf32 bits); g_x natural fp32.
__device__ float g_q[BB*DD*NN];
__device__ float g_k[BB*DD*NN];
__device__ float g_v[BB*DD*NN];
__device__ float g_x[BB*DD*NN];

// ---------------- packed f32x2 helpers ----------------
__device__ __forceinline__ void ffma2(u64& d, u64 a, u64 b) {
    asm("fma.rn.f32x2 %0, %1, %2, %3;" : "=l"(d) : "l"(a), "l"(b), "l"(d));
}
__device__ __forceinline__ u64 bcast2(float x) {
    u64 r; asm("mov.b64 %0, {%1, %1};" : "=l"(r) : "f"(x)); return r;
}
__device__ __forceinline__ float2 unpk(u64 v) {
    float lo, hi; asm("mov.b64 {%0, %1}, %2;" : "=f"(lo), "=f"(hi) : "l"(v));
    return make_float2(lo, hi);
}
__device__ __forceinline__ u32 f2tf32(float x) {
    u32 r; asm("cvt.rna.tf32.f32 %0, %1;" : "=r"(r) : "f"(x)); return r;
}
__device__ __forceinline__ u32 smem_u32(const void* p) {
    u32 a; asm("{ .reg .u64 t; cvta.to.shared.u64 t, %1; cvt.u32.u64 %0, t; }" : "=r"(a) : "l"(p));
    return a;
}
__device__ __forceinline__ void mma_tf32(float c[4], u32 a0, u32 a1, u32 a2, u32 a3,
                                         u32 b0, u32 b1) {
    asm volatile("mma.sync.aligned.m16n8k8.row.col.f32.tf32.tf32.f32 "
        "{%0,%1,%2,%3}, {%4,%5,%6,%7}, {%8,%9}, {%0,%1,%2,%3};"
        : "+f"(c[0]), "+f"(c[1]), "+f"(c[2]), "+f"(c[3])
        : "r"(a0), "r"(a1), "r"(a2), "r"(a3), "r"(b0), "r"(b1));
}
#define LDSM4(r, a) asm volatile( \
    "ldmatrix.sync.aligned.m8n8.x4.shared.b16 {%0,%1,%2,%3}, [%4];" \
    : "=r"((r)[0]), "=r"((r)[1]), "=r"((r)[2]), "=r"((r)[3]) : "r"(a))
#define STS2(a, x, y) asm volatile( \
    "st.shared.v2.b32 [%0], {%1,%2};" :: "r"(a), "r"(x), "r"(y) : "memory")
#define CPA16(dst, src) asm volatile( \
    "cp.async.cg.shared.global [%0], [%1], 16;" :: "r"(dst), "l"(src) : "memory")
#define CPA_COMMIT() asm volatile("cp.async.commit_group;" ::: "memory")
#define CPA_WAIT0()  asm volatile("cp.async.wait_group 0;" ::: "memory")

// ---------------------------------------------------------------------------
// Projection GEMM (fp32 exact, f32x2, o-pair packed). 64o x 128n tile, 256 thr.
// TRANS=1 writes per-head transposed [b][h][tok][dd].
// CVT=1 rounds output to tf32 bit pattern; SCALE=1 multiplies by 0.125 first.
// ---------------------------------------------------------------------------
template <int TRANS, int CVT, int SCALE>
__global__ __launch_bounds__(256) void proj_kernel(
    const float* __restrict__ W, const float* __restrict__ bias,
    const float* __restrict__ X, float* __restrict__ Y)
{
    __shared__ float sW[16*68];
    __shared__ float sX[16*132];

    const int b  = blockIdx.z;
    const int o0 = blockIdx.y * 64;
    const int n0 = blockIdx.x * 128;
    const int t  = threadIdx.x;
    const int tx = t & 31;
    const int ty = t >> 5;

    const float* Xb = X + (size_t)b * DD * NN;
    u64 acc2[4][4];
#pragma unroll
    for (int i = 0; i < 4; i++)
#pragma unroll
        for (int j = 0; j < 4; j++) acc2[i][j] = 0ull;

    for (int k0 = 0; k0 < DD; k0 += 16) {
#pragma unroll
        for (int i = 0; i < 4; i++) {
            int idx = t + i * 256;
            int oo = idx >> 4, kk = idx & 15;
            sW[kk * 68 + oo] = W[(o0 + oo) * DD + k0 + kk];
        }
#pragma unroll
        for (int i = 0; i < 2; i++) {
            int idx4 = t + i * 256;
            int kk = idx4 >> 5, c4 = idx4 & 31;
            *(float4*)&sX[kk * 132 + c4 * 4] =
                *(const float4*)&Xb[(k0 + kk) * NN + n0 + c4 * 4];
        }
        __syncthreads();
#pragma unroll
        for (int kk = 0; kk < 16; kk++) {
            const ulonglong2 w01 = *(const ulonglong2*)&sW[kk * 68 + ty * 8];
            const ulonglong2 w23 = *(const ulonglong2*)&sW[kk * 68 + ty * 8 + 4];
            const float4 xv = *(const float4*)&sX[kk * 132 + tx * 4];
            u64 x0 = bcast2(xv.x), x1 = bcast2(xv.y), x2 = bcast2(xv.z), x3 = bcast2(xv.w);
            ffma2(acc2[0][0], w01.x, x0); ffma2(acc2[0][1], w01.x, x1);
            ffma2(acc2[0][2], w01.x, x2); ffma2(acc2[0][3], w01.x, x3);
            ffma2(acc2[1][0], w01.y, x0); ffma2(acc2[1][1], w01.y, x1);
            ffma2(acc2[1][2], w01.y, x2); ffma2(acc2[1][3], w01.y, x3);
            ffma2(acc2[2][0], w23.x, x0); ffma2(acc2[2][1], w23.x, x1);
            ffma2(acc2[2][2], w23.x, x2); ffma2(acc2[2][3], w23.x, x3);
            ffma2(acc2[3][0], w23.y, x0); ffma2(acc2[3][1], w23.y, x1);
            ffma2(acc2[3][2], w23.y, x2); ffma2(acc2[3][3], w23.y, x3);
        }
        __syncthreads();
    }

    float v[8][4];
#pragma unroll
    for (int op = 0; op < 4; op++)
#pragma unroll
        for (int n = 0; n < 4; n++) {
            float2 p = unpk(acc2[op][n]);
            v[op * 2][n] = p.x;
            v[op * 2 + 1][n] = p.y;
        }
#pragma unroll
    for (int oi = 0; oi < 8; oi++) {
        int o = o0 + ty * 8 + oi;
        float bv = bias[o];
        float v4[4];
#pragma unroll
        for (int n = 0; n < 4; n++) {
            float val = v[oi][n] + bv;
            if (SCALE) val *= 0.125f;
            if (CVT) val = __uint_as_float(f2tf32(val));
            v4[n] = val;
        }
        if (TRANS) {
            int dd = o >> 2, hh = o & 3;
            float* base = Y + (((size_t)b * NH + hh) * NN + n0 + tx * 4) * HD + dd;
#pragma unroll
            for (int n = 0; n < 4; n++) base[n * HD] = v4[n];
        } else {
            float* Yb = Y + (size_t)b * DD * NN;
            *(float4*)&Yb[o * NN + n0 + tx * 4] = make_float4(v4[0], v4[1], v4[2], v4[3]);
        }
    }
}

// ---------------------------------------------------------------------------
// mma.sync tf32 flash attention. CTA = (b, h, 128-q tile), 256 threads,
// 8 warps as 4(m: 32 q rows) x 2(n: 32 cols). ldmatrix + swizzled tiles.
// Inputs are pre-converted tf32 bits (q pre-scaled by 1/8) -> cp.async fills.
// SMEM: sQ[128][64], sK[64][64](tok,dd), sV[64][64](dd,tok), sP[128][64].
// Row = 64 u32 = 256 B = 16 chunks of 16 B; chunk' = chunk ^ (row & 7).
// ---------------------------------------------------------------------------
__global__ __launch_bounds__(256, 2) void attn_mma(const int* __restrict__ mask)
{
    extern __shared__ u32 smu[];
    const u32 sbase = smem_u32(smu);
    const u32 Qo = 0;
    const u32 Ko = 32768;
    const u32 Vo = 49152;
    const u32 Po = 65536;
    float* skmf = (float*)(smu + 24576);     // 64 floats
    float* sL = (float*)(smu + 24640);       // [2][128]

    const int t = threadIdx.x;
    const int w = t >> 5, lane = t & 31;
    const int wm = w >> 1, wn = w & 1;
    const int gid = lane >> 2, tig = lane & 3;
    const int b = blockIdx.z, h = blockIdx.y;
    const int q0 = blockIdx.x * QTILE;

    // ldmatrix address components
    const int arow0 = wm * 32 + (lane & 15);      // A rows (mi adds 16)
    const int ahi = lane >> 4;                    // chunk +1 for col+4 matrices
    const int brow8 = ((lane >> 4) << 3) + (lane & 7);  // B x4: row within 16-row pair-block
    const int bhi = (lane >> 3) & 1;

    // ---- Q fill via cp.async (already tf32, pre-scaled) ----
    const float* qb = g_q + (((size_t)b * NH + h) * NN + q0) * HD;
#pragma unroll
    for (int i = 0; i < 2; i++) {
        int idx = t + i * 256;
        int row = idx >> 2, c4 = (idx & 3) * 4;
        // each thread copies 4 chunks along the row (c4..c4+3)
#pragma unroll
        for (int j = 0; j < 4; j++) {
            int c = c4 + j;
            u32 a = sbase + Qo + row * 256 + ((c ^ (row & 7)) << 4);
            CPA16(a, qb + row * HD + c * 4);
        }
    }

    const int* mb_ = mask + (size_t)b * NN;
    float qmf[4];
    qmf[0] = (float)mb_[q0 + wm * 32 + gid];
    qmf[1] = (float)mb_[q0 + wm * 32 + gid + 8];
    qmf[2] = (float)mb_[q0 + wm * 32 + gid + 16];
    qmf[3] = (float)mb_[q0 + wm * 32 + gid + 24];

    float oc[2][4][4];
#pragma unroll
    for (int mi = 0; mi < 2; mi++)
#pragma unroll
        for (int nb = 0; nb < 4; nb++)
#pragma unroll
            for (int e = 0; e < 4; e++) oc[mi][nb][e] = 0.f;
    float lsum[4] = {0.f, 0.f, 0.f, 0.f};

    const float* kb0 = g_k + (((size_t)b * NH + h) * NN) * HD;
    const float* vb0 = g_v + ((size_t)b * DD + h) * NN;

    for (int k0 = 0; k0 < NN; k0 += KTILE) {
        __syncthreads();   // prev-iter reads of sK/sV/sP done; Q fill target safe
        // ---- K fill: [tok][dd], 4 chunks/thread ----
        {
            int row = t >> 2, c4 = (t & 3) * 4;
            const float* src = kb0 + (size_t)(k0 + row) * HD + c4 * 4;
#pragma unroll
            for (int j = 0; j < 4; j++) {
                int c = c4 + j;
                u32 a = sbase + Ko + row * 256 + ((c ^ (row & 7)) << 4);
                CPA16(a, src + j * 4);
            }
        }
        // ---- V fill: [dd][tok], 4 chunks/thread ----
        {
            int dd = t >> 2, c4 = (t & 3) * 4;
            const float* src = vb0 + (size_t)dd * (NH * NN) + k0 + c4 * 4;
#pragma unroll
            for (int j = 0; j < 4; j++) {
                int c = c4 + j;
                u32 a = sbase + Vo + dd * 256 + ((c ^ (dd & 7)) << 4);
                CPA16(a, src + j * 4);
            }
        }
        if (t < KTILE) skmf[t] = (float)mb_[k0 + t];
        CPA_COMMIT();
        CPA_WAIT0();
        __syncthreads();

        // ---- S = Q K^T (warp block: 32 q x 32 k) ----
        float sc[2][4][4];
#pragma unroll
        for (int mi = 0; mi < 2; mi++)
#pragma unroll
            for (int nb = 0; nb < 4; nb++)
#pragma unroll
                for (int e = 0; e < 4; e++) sc[mi][nb][e] = 0.f;
#pragma unroll
        for (int ks = 0; ks < 8; ks++) {
            u32 A0[4], A1[4];
            {
                int r = arow0;
                u32 a = sbase + Qo + r * 256 + (((ks * 2 + ahi) ^ (r & 7)) << 4);
                LDSM4(A0, a);
                r = arow0 + 16;
                a = sbase + Qo + r * 256 + (((ks * 2 + ahi) ^ (r & 7)) << 4);
                LDSM4(A1, a);
            }
#pragma unroll
            for (int nbp = 0; nbp < 2; nbp++) {
                int rr = wn * 32 + nbp * 16 + brow8;
                u32 ab = sbase + Ko + rr * 256 + (((ks * 2 + bhi) ^ (rr & 7)) << 4);
                u32 B[4]; LDSM4(B, ab);
                mma_tf32(sc[0][nbp*2],   A0[0], A0[1], A0[2], A0[3], B[0], B[1]);
                mma_tf32(sc[1][nbp*2],   A1[0], A1[1], A1[2], A1[3], B[0], B[1]);
                mma_tf32(sc[0][nbp*2+1], A0[0], A0[1], A0[2], A0[3], B[2], B[3]);
                mma_tf32(sc[1][nbp*2+1], A1[0], A1[1], A1[2], A1[3], B[2], B[3]);
            }
        }

        // ---- softmax (no-max, multiply-mask), P -> sP ----
#pragma unroll
        for (int nb = 0; nb < 4; nb++) {
            int col0 = wn * 32 + nb * 8 + tig * 2;
            float km0 = skmf[col0], km1 = skmf[col0 + 1];
            float e0 = __expf(sc[0][nb][0]) * qmf[0] * km0;
            float e1 = __expf(sc[0][nb][1]) * qmf[0] * km1;
            float e2 = __expf(sc[0][nb][2]) * qmf[1] * km0;
            float e3 = __expf(sc[0][nb][3]) * qmf[1] * km1;
            float f0 = __expf(sc[1][nb][0]) * qmf[2] * km0;
            float f1 = __expf(sc[1][nb][1]) * qmf[2] * km1;
            float f2 = __expf(sc[1][nb][2]) * qmf[3] * km0;
            float f3 = __expf(sc[1][nb][3]) * qmf[3] * km1;
            lsum[0] += e0 + e1; lsum[1] += e2 + e3;
            lsum[2] += f0 + f1; lsum[3] += f2 + f3;
            int ch = col0 >> 2;
            int r0 = wm * 32 + gid;
            u32 a0 = sbase + Po + r0 * 256 + ((ch ^ (r0 & 7)) << 4) + (tig & 1) * 8;
            STS2(a0, f2tf32(e0), f2tf32(e1));
            int r1 = r0 + 8;
            u32 a1 = sbase + Po + r1 * 256 + ((ch ^ (r1 & 7)) << 4) + (tig & 1) * 8;
            STS2(a1, f2tf32(e2), f2tf32(e3));
            int r2 = r0 + 16;
            u32 a2 = sbase + Po + r2 * 256 + ((ch ^ (r2 & 7)) << 4) + (tig & 1) * 8;
            STS2(a2, f2tf32(f0), f2tf32(f1));
            int r3 = r0 + 24;
            u32 a3 = sbase + Po + r3 * 256 + ((ch ^ (r3 & 7)) << 4) + (tig & 1) * 8;
            STS2(a3, f2tf32(f2), f2tf32(f3));
        }
        __syncthreads();   // P visible to both n-warps

        // ---- O += P V (kt-outer) ----
#pragma unroll
        for (int kt = 0; kt < 8; kt++) {
            u32 A0[4], A1[4];
            {
                int r = arow0;
                u32 a = sbase + Po + r * 256 + (((kt * 2 + ahi) ^ (r & 7)) << 4);
                LDSM4(A0, a);
                r = arow0 + 16;
                a = sbase + Po + r * 256 + (((kt * 2 + ahi) ^ (r & 7)) << 4);
                LDSM4(A1, a);
            }
#pragma unroll
            for (int nbp = 0; nbp < 2; nbp++) {
                int rr = wn * 32 + nbp * 16 + brow8;
                u32 ab = sbase + Vo + rr * 256 + (((kt * 2 + bhi) ^ (rr & 7)) << 4);
                u32 B[4]; LDSM4(B, ab);
                mma_tf32(oc[0][nbp*2],   A0[0], A0[1], A0[2], A0[3], B[0], B[1]);
                mma_tf32(oc[1][nbp*2],   A1[0], A1[1], A1[2], A1[3], B[0], B[1]);
                mma_tf32(oc[0][nbp*2+1], A0[0], A0[1], A0[2], A0[3], B[2], B[3]);
                mma_tf32(oc[1][nbp*2+1], A1[0], A1[1], A1[2], A1[3], B[2], B[3]);
            }
        }
    }

    // ---- reduce l across tig lanes, then across n-warps via smem ----
#pragma unroll
    for (int i = 0; i < 4; i++) {
        lsum[i] += __shfl_xor_sync(~0u, lsum[i], 1);
        lsum[i] += __shfl_xor_sync(~0u, lsum[i], 2);
    }
    if (tig == 0) {
        sL[wn * 128 + wm * 32 + gid]      = lsum[0];
        sL[wn * 128 + wm * 32 + gid + 8]  = lsum[1];
        sL[wn * 128 + wm * 32 + gid + 16] = lsum[2];
        sL[wn * 128 + wm * 32 + gid + 24] = lsum[3];
    }
    __syncthreads();
    float inv[4];
#pragma unroll
    for (int i = 0; i < 4; i++) {
        int rl = wm * 32 + ((i & 1) ? 8 : 0) + ((i >> 1) ? 16 : 0) + gid;
        inv[i] = 1.f / (sL[rl] + sL[128 + rl]);
    }

    // ---- epilogue ----
    float* xb = g_x + ((size_t)b * DD + h) * NN;
#pragma unroll
    for (int mi = 0; mi < 2; mi++) {
        int r0 = q0 + wm * 32 + mi * 16 + gid;
        int r1 = r0 + 8;
#pragma unroll
        for (int nb = 0; nb < 4; nb++) {
            int dd0 = wn * 32 + nb * 8 + tig * 2;
            xb[(size_t)dd0 * (NH * NN) + r0]       = oc[mi][nb][0] * inv[2*mi];
            xb[(size_t)(dd0 + 1) * (NH * NN) + r0] = oc[mi][nb][1] * inv[2*mi];
            xb[(size_t)dd0 * (NH * NN) + r1]       = oc[mi][nb][2] * inv[2*mi+1];
            xb[(size_t)(dd0 + 1) * (NH * NN) + r1] = oc[mi][nb][3] * inv[2*mi+1];
        }
    }
}

// ---------------------------------------------------------------------------
extern "C" void kernel_launch(void* const* d_in, const int* in_sizes, int n_in,
                              void* d_out, int out_size)
{
    const float* query = (const float*)d_in[0];
    const float* key_  = (const float*)d_in[1];
    const float* value = (const float*)d_in[2];
    const int*   mask  = (const int*)  d_in[3];
    const float* Wq = (const float*)d_in[4];
    const float* bq = (const float*)d_in[5];
    const float* Wk = (const float*)d_in[6];
    const float* bk = (const float*)d_in[7];
    const float* Wv = (const float*)d_in[8];
    const float* bv = (const float*)d_in[9];
    const float* Wm = (const float*)d_in[10];
    const float* bm = (const float*)d_in[11];
    float* out = (float*)d_out;

    float *q, *k, *v, *x;
    cudaGetSymbolAddress((void**)&q, g_q);
    cudaGetSymbolAddress((void**)&k, g_k);
    cudaGetSymbolAddress((void**)&v, g_v);
    cudaGetSymbolAddress((void**)&x, g_x);

    dim3 pgrid(NN / 128, DD / 64, BB);
    proj_kernel<1, 1, 1><<<pgrid, 256>>>(Wq, bq, query, q);   // q: tf32(q/8)
    proj_kernel<1, 1, 0><<<pgrid, 256>>>(Wk, bk, key_,  k);   // k: tf32(k)
    proj_kernel<0, 1, 0><<<pgrid, 256>>>(Wv, bv, value, v);   // v: tf32(v)

    const int asmem = 98304 + 64 * 4 + 2 * 128 * 4;  // 99584
    cudaFuncSetAttribute(attn_mma, cudaFuncAttributeMaxDynamicSharedMemorySize, asmem);
    dim3 agrid(NN / QTILE, NH, BB);
    attn_mma<<<agrid, 256, asmem>>>(mask);

    proj_kernel<0, 0, 0><<<pgrid, 256>>>(Wm, bm, x, out);
}

// round 10
// speedup vs baseline: 2.5349x; 1.2691x over previous
#include <cuda_runtime.h>
#include <math.h>
#include <stdint.h>

#define BB 8
#define DD 256
#define NN 2048
#define NH 4
#define HD 64
#define QTILE 128
#define KTILE 64

typedef unsigned long long u64;
typedef unsigned int u32;

// Scratch. g_q/g_k TRANSPOSED per-head [b][h][tok][dd] (tf32 bits, q pre-scaled);
// g_v natural [b][ch][tok] (tf32 bits); g_x natural fp32.
__device__ float g_q[BB*DD*NN];
__device__ float g_k[BB*DD*NN];
__device__ float g_v[BB*DD*NN];
__device__ float g_x[BB*DD*NN];

// ---------------- packed f32x2 helpers ----------------
__device__ __forceinline__ void ffma2(u64& d, u64 a, u64 b) {
    asm("fma.rn.f32x2 %0, %1, %2, %3;" : "=l"(d) : "l"(a), "l"(b), "l"(d));
}
__device__ __forceinline__ u64 bcast2(float x) {
    u64 r; asm("mov.b64 %0, {%1, %1};" : "=l"(r) : "f"(x)); return r;
}
__device__ __forceinline__ float2 unpk(u64 v) {
    float lo, hi; asm("mov.b64 {%0, %1}, %2;" : "=f"(lo), "=f"(hi) : "l"(v));
    return make_float2(lo, hi);
}
__device__ __forceinline__ u32 f2tf32(float x) {
    u32 r; asm("cvt.rna.tf32.f32 %0, %1;" : "=r"(r) : "f"(x)); return r;
}
__device__ __forceinline__ u32 smem_u32(const void* p) {
    u32 a; asm("{ .reg .u64 t; cvta.to.shared.u64 t, %1; cvt.u32.u64 %0, t; }" : "=r"(a) : "l"(p));
    return a;
}
__device__ __forceinline__ void mma_tf32(float c[4], u32 a0, u32 a1, u32 a2, u32 a3,
                                         u32 b0, u32 b1) {
    asm volatile("mma.sync.aligned.m16n8k8.row.col.f32.tf32.tf32.f32 "
        "{%0,%1,%2,%3}, {%4,%5,%6,%7}, {%8,%9}, {%0,%1,%2,%3};"
        : "+f"(c[0]), "+f"(c[1]), "+f"(c[2]), "+f"(c[3])
        : "r"(a0), "r"(a1), "r"(a2), "r"(a3), "r"(b0), "r"(b1));
}
#define LDSM4(r, a) asm volatile( \
    "ldmatrix.sync.aligned.m8n8.x4.shared.b16 {%0,%1,%2,%3}, [%4];" \
    : "=r"((r)[0]), "=r"((r)[1]), "=r"((r)[2]), "=r"((r)[3]) : "r"(a))
#define STS2(a, x, y) asm volatile( \
    "st.shared.v2.b32 [%0], {%1,%2};" :: "r"(a), "r"(x), "r"(y) : "memory")
#define STS4(a, x, y, z, w_) asm volatile( \
    "st.shared.v4.b32 [%0], {%1,%2,%3,%4};" :: "r"(a), "r"(x), "r"(y), "r"(z), "r"(w_) : "memory")
#define CPA16(dst, src) asm volatile( \
    "cp.async.cg.shared.global [%0], [%1], 16;" :: "r"(dst), "l"(src) : "memory")
#define CPA_COMMIT() asm volatile("cp.async.commit_group;" ::: "memory")
#define CPA_WAIT0()  asm volatile("cp.async.wait_group 0;" ::: "memory")

// ---------------------------------------------------------------------------
// Projection GEMM (fp32 exact, f32x2) — used only for the OUTPUT projection.
// ---------------------------------------------------------------------------
__global__ __launch_bounds__(256) void proj_kernel(
    const float* __restrict__ W, const float* __restrict__ bias,
    const float* __restrict__ X, float* __restrict__ Y)
{
    __shared__ float sW[16*68];
    __shared__ float sX[16*132];

    const int b  = blockIdx.z;
    const int o0 = blockIdx.y * 64;
    const int n0 = blockIdx.x * 128;
    const int t  = threadIdx.x;
    const int tx = t & 31;
    const int ty = t >> 5;

    const float* Xb = X + (size_t)b * DD * NN;
    u64 acc2[4][4];
#pragma unroll
    for (int i = 0; i < 4; i++)
#pragma unroll
        for (int j = 0; j < 4; j++) acc2[i][j] = 0ull;

    for (int k0 = 0; k0 < DD; k0 += 16) {
#pragma unroll
        for (int i = 0; i < 4; i++) {
            int idx = t + i * 256;
            int oo = idx >> 4, kk = idx & 15;
            sW[kk * 68 + oo] = W[(o0 + oo) * DD + k0 + kk];
        }
#pragma unroll
        for (int i = 0; i < 2; i++) {
            int idx4 = t + i * 256;
            int kk = idx4 >> 5, c4 = idx4 & 31;
            *(float4*)&sX[kk * 132 + c4 * 4] =
                *(const float4*)&Xb[(k0 + kk) * NN + n0 + c4 * 4];
        }
        __syncthreads();
#pragma unroll
        for (int kk = 0; kk < 16; kk++) {
            const ulonglong2 w01 = *(const ulonglong2*)&sW[kk * 68 + ty * 8];
            const ulonglong2 w23 = *(const ulonglong2*)&sW[kk * 68 + ty * 8 + 4];
            const float4 xv = *(const float4*)&sX[kk * 132 + tx * 4];
            u64 x0 = bcast2(xv.x), x1 = bcast2(xv.y), x2 = bcast2(xv.z), x3 = bcast2(xv.w);
            ffma2(acc2[0][0], w01.x, x0); ffma2(acc2[0][1], w01.x, x1);
            ffma2(acc2[0][2], w01.x, x2); ffma2(acc2[0][3], w01.x, x3);
            ffma2(acc2[1][0], w01.y, x0); ffma2(acc2[1][1], w01.y, x1);
            ffma2(acc2[1][2], w01.y, x2); ffma2(acc2[1][3], w01.y, x3);
            ffma2(acc2[2][0], w23.x, x0); ffma2(acc2[2][1], w23.x, x1);
            ffma2(acc2[2][2], w23.x, x2); ffma2(acc2[2][3], w23.x, x3);
            ffma2(acc2[3][0], w23.y, x0); ffma2(acc2[3][1], w23.y, x1);
            ffma2(acc2[3][2], w23.y, x2); ffma2(acc2[3][3], w23.y, x3);
        }
        __syncthreads();
    }

    float v[8][4];
#pragma unroll
    for (int op = 0; op < 4; op++)
#pragma unroll
        for (int n = 0; n < 4; n++) {
            float2 p = unpk(acc2[op][n]);
            v[op * 2][n] = p.x;
            v[op * 2 + 1][n] = p.y;
        }
#pragma unroll
    for (int oi = 0; oi < 8; oi++) {
        int o = o0 + ty * 8 + oi;
        float bv = bias[o];
        float* Yb = Y + (size_t)b * DD * NN;
        *(float4*)&Yb[o * NN + n0 + tx * 4] = make_float4(
            v[oi][0] + bv, v[oi][1] + bv, v[oi][2] + bv, v[oi][3] + bv);
    }
}

// ---------------------------------------------------------------------------
// tf32 mma projection for q/k/v. C[o][tok] = W[o][i] · X^T[tok][i] + bias.
// CTA = (64-token tile, 128-o tile, b), 256 threads, warps 4(m over o) x 2(n over tok).
// SMEM: A = W chunk [128 o][64 i] (32KB), B = X^T chunk [64 tok][64 i] (16KB).
// Same swizzle/fragment geometry as attention tiles (row=256B, chunk^(row&7)).
// TRANSQ=1: write per-head transposed tf32 [b][h][tok][dd]; SCALE folds 1/8.
// TRANSQ=0: write natural tf32 [b][ch][tok].
// ---------------------------------------------------------------------------
template <int TRANSQ, int SCALE>
__global__ __launch_bounds__(256, 2) void proj_mma(
    const float* __restrict__ W, const float* __restrict__ bias,
    const float* __restrict__ X, float* __restrict__ Y)
{
    extern __shared__ u32 psm[];
    const u32 sbase = smem_u32(psm);
    const u32 Ao = 0;          // 8192 u32
    const u32 Bo = 32768;      // 4096 u32

    const int t = threadIdx.x;
    const int w = t >> 5, lane = t & 31;
    const int wm = w >> 1, wn = w & 1;
    const int gid = lane >> 2, tig = lane & 3;
    const int b  = blockIdx.z;
    const int o0 = blockIdx.y * 128;
    const int n0 = blockIdx.x * 64;

    const int arow0 = wm * 32 + (lane & 15);
    const int ahi = lane >> 4;
    const int brow8 = ((lane >> 4) << 3) + (lane & 7);
    const int bhi = (lane >> 3) & 1;

    const float* Xb = X + (size_t)b * DD * NN;

    float oc[2][4][4];
#pragma unroll
    for (int mi = 0; mi < 2; mi++)
#pragma unroll
        for (int nb = 0; nb < 4; nb++)
#pragma unroll
            for (int e = 0; e < 4; e++) oc[mi][nb][e] = 0.f;

    for (int kc = 0; kc < DD; kc += 64) {
        __syncthreads();
        // ---- A fill: W [128 o][64 i], float4 loads + cvt ----
#pragma unroll
        for (int i = 0; i < 8; i++) {
            int idx = t + i * 256;
            int row = idx >> 4, c = idx & 15;
            float4 wv = *(const float4*)&W[(size_t)(o0 + row) * DD + kc + c * 4];
            u32 a = sbase + Ao + row * 256 + ((c ^ (row & 7)) << 4);
            STS4(a, f2tf32(wv.x), f2tf32(wv.y), f2tf32(wv.z), f2tf32(wv.w));
        }
        // ---- B fill: X^T [64 tok][64 i], transpose gather + cvt ----
#pragma unroll
        for (int i = 0; i < 4; i++) {
            int idx = t + i * 256;
            int tok = idx & 63, kq = idx >> 6;  // kq 0..15
            const float* src = Xb + (size_t)(kc + kq * 4) * NN + n0 + tok;
            u32 v0 = f2tf32(src[0]);
            u32 v1 = f2tf32(src[NN]);
            u32 v2 = f2tf32(src[2 * NN]);
            u32 v3 = f2tf32(src[3 * NN]);
            u32 a = sbase + Bo + tok * 256 + ((kq ^ (tok & 7)) << 4);
            STS4(a, v0, v1, v2, v3);
        }
        __syncthreads();

        // ---- C += A B^T (identical geometry to attention S-GEMM) ----
#pragma unroll
        for (int ks = 0; ks < 8; ks++) {
            u32 A0[4], A1[4];
            {
                int r = arow0;
                u32 a = sbase + Ao + r * 256 + (((ks * 2 + ahi) ^ (r & 7)) << 4);
                LDSM4(A0, a);
                r = arow0 + 16;
                a = sbase + Ao + r * 256 + (((ks * 2 + ahi) ^ (r & 7)) << 4);
                LDSM4(A1, a);
            }
#pragma unroll
            for (int nbp = 0; nbp < 2; nbp++) {
                int rr = wn * 32 + nbp * 16 + brow8;
                u32 ab = sbase + Bo + rr * 256 + (((ks * 2 + bhi) ^ (rr & 7)) << 4);
                u32 B[4]; LDSM4(B, ab);
                mma_tf32(oc[0][nbp*2],   A0[0], A0[1], A0[2], A0[3], B[0], B[1]);
                mma_tf32(oc[1][nbp*2],   A1[0], A1[1], A1[2], A1[3], B[0], B[1]);
                mma_tf32(oc[0][nbp*2+1], A0[0], A0[1], A0[2], A0[3], B[2], B[3]);
                mma_tf32(oc[1][nbp*2+1], A1[0], A1[1], A1[2], A1[3], B[2], B[3]);
            }
        }
    }

    // ---- epilogue ----
    float bv[2][2];
#pragma unroll
    for (int mi = 0; mi < 2; mi++) {
        bv[mi][0] = bias[o0 + wm * 32 + mi * 16 + gid];
        bv[mi][1] = bias[o0 + wm * 32 + mi * 16 + gid + 8];
    }
#pragma unroll
    for (int mi = 0; mi < 2; mi++)
#pragma unroll
    for (int nb = 0; nb < 4; nb++) {
        int token = n0 + wn * 32 + nb * 8 + tig * 2;
        float v0 = oc[mi][nb][0] + bv[mi][0];
        float v1 = oc[mi][nb][1] + bv[mi][0];
        float v2 = oc[mi][nb][2] + bv[mi][1];
        float v3 = oc[mi][nb][3] + bv[mi][1];
        if (SCALE) { v0 *= 0.125f; v1 *= 0.125f; v2 *= 0.125f; v3 *= 0.125f; }
        u32 t0 = f2tf32(v0), t1 = f2tf32(v1), t2 = f2tf32(v2), t3 = f2tf32(v3);
        int o = o0 + wm * 32 + mi * 16 + gid;
        if (TRANSQ) {
            // [b][h][tok][dd], h = o&3, dd = o>>2
            {
                float* d = Y + (((size_t)b * NH + (o & 3)) * NN + token) * HD + (o >> 2);
                d[0]  = __uint_as_float(t0);
                d[HD] = __uint_as_float(t1);
            }
            {
                int o2 = o + 8;
                float* d = Y + (((size_t)b * NH + (o2 & 3)) * NN + token) * HD + (o2 >> 2);
                d[0]  = __uint_as_float(t2);
                d[HD] = __uint_as_float(t3);
            }
        } else {
            *(float2*)&Y[((size_t)b * DD + o) * NN + token] =
                make_float2(__uint_as_float(t0), __uint_as_float(t1));
            *(float2*)&Y[((size_t)b * DD + o + 8) * NN + token] =
                make_float2(__uint_as_float(t2), __uint_as_float(t3));
        }
    }
}

// ---------------------------------------------------------------------------
// mma.sync tf32 flash attention (unchanged from R8).
// ---------------------------------------------------------------------------
__global__ __launch_bounds__(256, 2) void attn_mma(const int* __restrict__ mask)
{
    extern __shared__ u32 smu[];
    const u32 sbase = smem_u32(smu);
    const u32 Qo = 0;
    const u32 Ko = 32768;
    const u32 Vo = 49152;
    const u32 Po = 65536;
    float* skmf = (float*)(smu + 24576);
    float* sL = (float*)(smu + 24640);

    const int t = threadIdx.x;
    const int w = t >> 5, lane = t & 31;
    const int wm = w >> 1, wn = w & 1;
    const int gid = lane >> 2, tig = lane & 3;
    const int b = blockIdx.z, h = blockIdx.y;
    const int q0 = blockIdx.x * QTILE;

    const int arow0 = wm * 32 + (lane & 15);
    const int ahi = lane >> 4;
    const int brow8 = ((lane >> 4) << 3) + (lane & 7);
    const int bhi = (lane >> 3) & 1;

    const float* qb = g_q + (((size_t)b * NH + h) * NN + q0) * HD;
#pragma unroll
    for (int i = 0; i < 2; i++) {
        int idx = t + i * 256;
        int row = idx >> 2, c4 = (idx & 3) * 4;
#pragma unroll
        for (int j = 0; j < 4; j++) {
            int c = c4 + j;
            u32 a = sbase + Qo + row * 256 + ((c ^ (row & 7)) << 4);
            CPA16(a, qb + row * HD + c * 4);
        }
    }

    const int* mb_ = mask + (size_t)b * NN;
    float qmf[4];
    qmf[0] = (float)mb_[q0 + wm * 32 + gid];
    qmf[1] = (float)mb_[q0 + wm * 32 + gid + 8];
    qmf[2] = (float)mb_[q0 + wm * 32 + gid + 16];
    qmf[3] = (float)mb_[q0 + wm * 32 + gid + 24];

    float oc[2][4][4];
#pragma unroll
    for (int mi = 0; mi < 2; mi++)
#pragma unroll
        for (int nb = 0; nb < 4; nb++)
#pragma unroll
            for (int e = 0; e < 4; e++) oc[mi][nb][e] = 0.f;
    float lsum[4] = {0.f, 0.f, 0.f, 0.f};

    const float* kb0 = g_k + (((size_t)b * NH + h) * NN) * HD;
    const float* vb0 = g_v + ((size_t)b * DD + h) * NN;

    for (int k0 = 0; k0 < NN; k0 += KTILE) {
        __syncthreads();
        {
            int row = t >> 2, c4 = (t & 3) * 4;
            const float* src = kb0 + (size_t)(k0 + row) * HD + c4 * 4;
#pragma unroll
            for (int j = 0; j < 4; j++) {
                int c = c4 + j;
                u32 a = sbase + Ko + row * 256 + ((c ^ (row & 7)) << 4);
                CPA16(a, src + j * 4);
            }
        }
        {
            int dd = t >> 2, c4 = (t & 3) * 4;
            const float* src = vb0 + (size_t)dd * (NH * NN) + k0 + c4 * 4;
#pragma unroll
            for (int j = 0; j < 4; j++) {
                int c = c4 + j;
                u32 a = sbase + Vo + dd * 256 + ((c ^ (dd & 7)) << 4);
                CPA16(a, src + j * 4);
            }
        }
        if (t < KTILE) skmf[t] = (float)mb_[k0 + t];
        CPA_COMMIT();
        CPA_WAIT0();
        __syncthreads();

        float sc[2][4][4];
#pragma unroll
        for (int mi = 0; mi < 2; mi++)
#pragma unroll
            for (int nb = 0; nb < 4; nb++)
#pragma unroll
                for (int e = 0; e < 4; e++) sc[mi][nb][e] = 0.f;
#pragma unroll
        for (int ks = 0; ks < 8; ks++) {
            u32 A0[4], A1[4];
            {
                int r = arow0;
                u32 a = sbase + Qo + r * 256 + (((ks * 2 + ahi) ^ (r & 7)) << 4);
                LDSM4(A0, a);
                r = arow0 + 16;
                a = sbase + Qo + r * 256 + (((ks * 2 + ahi) ^ (r & 7)) << 4);
                LDSM4(A1, a);
            }
#pragma unroll
            for (int nbp = 0; nbp < 2; nbp++) {
                int rr = wn * 32 + nbp * 16 + brow8;
                u32 ab = sbase + Ko + rr * 256 + (((ks * 2 + bhi) ^ (rr & 7)) << 4);
                u32 B[4]; LDSM4(B, ab);
                mma_tf32(sc[0][nbp*2],   A0[0], A0[1], A0[2], A0[3], B[0], B[1]);
                mma_tf32(sc[1][nbp*2],   A1[0], A1[1], A1[2], A1[3], B[0], B[1]);
                mma_tf32(sc[0][nbp*2+1], A0[0], A0[1], A0[2], A0[3], B[2], B[3]);
                mma_tf32(sc[1][nbp*2+1], A1[0], A1[1], A1[2], A1[3], B[2], B[3]);
            }
        }

#pragma unroll
        for (int nb = 0; nb < 4; nb++) {
            int col0 = wn * 32 + nb * 8 + tig * 2;
            float km0 = skmf[col0], km1 = skmf[col0 + 1];
            float e0 = __expf(sc[0][nb][0]) * qmf[0] * km0;
            float e1 = __expf(sc[0][nb][1]) * qmf[0] * km1;
            float e2 = __expf(sc[0][nb][2]) * qmf[1] * km0;
            float e3 = __expf(sc[0][nb][3]) * qmf[1] * km1;
            float f0 = __expf(sc[1][nb][0]) * qmf[2] * km0;
            float f1 = __expf(sc[1][nb][1]) * qmf[2] * km1;
            float f2 = __expf(sc[1][nb][2]) * qmf[3] * km0;
            float f3 = __expf(sc[1][nb][3]) * qmf[3] * km1;
            lsum[0] += e0 + e1; lsum[1] += e2 + e3;
            lsum[2] += f0 + f1; lsum[3] += f2 + f3;
            int ch = col0 >> 2;
            int r0 = wm * 32 + gid;
            u32 a0 = sbase + Po + r0 * 256 + ((ch ^ (r0 & 7)) << 4) + (tig & 1) * 8;
            STS2(a0, f2tf32(e0), f2tf32(e1));
            int r1 = r0 + 8;
            u32 a1 = sbase + Po + r1 * 256 + ((ch ^ (r1 & 7)) << 4) + (tig & 1) * 8;
            STS2(a1, f2tf32(e2), f2tf32(e3));
            int r2 = r0 + 16;
            u32 a2 = sbase + Po + r2 * 256 + ((ch ^ (r2 & 7)) << 4) + (tig & 1) * 8;
            STS2(a2, f2tf32(f0), f2tf32(f1));
            int r3 = r0 + 24;
            u32 a3 = sbase + Po + r3 * 256 + ((ch ^ (r3 & 7)) << 4) + (tig & 1) * 8;
            STS2(a3, f2tf32(f2), f2tf32(f3));
        }
        __syncthreads();

#pragma unroll
        for (int kt = 0; kt < 8; kt++) {
            u32 A0[4], A1[4];
            {
                int r = arow0;
                u32 a = sbase + Po + r * 256 + (((kt * 2 + ahi) ^ (r & 7)) << 4);
                LDSM4(A0, a);
                r = arow0 + 16;
                a = sbase + Po + r * 256 + (((kt * 2 + ahi) ^ (r & 7)) << 4);
                LDSM4(A1, a);
            }
#pragma unroll
            for (int nbp = 0; nbp < 2; nbp++) {
                int rr = wn * 32 + nbp * 16 + brow8;
                u32 ab = sbase + Vo + rr * 256 + (((kt * 2 + bhi) ^ (rr & 7)) << 4);
                u32 B[4]; LDSM4(B, ab);
                mma_tf32(oc[0][nbp*2],   A0[0], A0[1], A0[2], A0[3], B[0], B[1]);
                mma_tf32(oc[1][nbp*2],   A1[0], A1[1], A1[2], A1[3], B[0], B[1]);
                mma_tf32(oc[0][nbp*2+1], A0[0], A0[1], A0[2], A0[3], B[2], B[3]);
                mma_tf32(oc[1][nbp*2+1], A1[0], A1[1], A1[2], A1[3], B[2], B[3]);
            }
        }
    }

#pragma unroll
    for (int i = 0; i < 4; i++) {
        lsum[i] += __shfl_xor_sync(~0u, lsum[i], 1);
        lsum[i] += __shfl_xor_sync(~0u, lsum[i], 2);
    }
    if (tig == 0) {
        sL[wn * 128 + wm * 32 + gid]      = lsum[0];
        sL[wn * 128 + wm * 32 + gid + 8]  = lsum[1];
        sL[wn * 128 + wm * 32 + gid + 16] = lsum[2];
        sL[wn * 128 + wm * 32 + gid + 24] = lsum[3];
    }
    __syncthreads();
    float inv[4];
#pragma unroll
    for (int i = 0; i < 4; i++) {
        int rl = wm * 32 + ((i & 1) ? 8 : 0) + ((i >> 1) ? 16 : 0) + gid;
        inv[i] = 1.f / (sL[rl] + sL[128 + rl]);
    }

    float* xb = g_x + ((size_t)b * DD + h) * NN;
#pragma unroll
    for (int mi = 0; mi < 2; mi++) {
        int r0 = q0 + wm * 32 + mi * 16 + gid;
        int r1 = r0 + 8;
#pragma unroll
        for (int nb = 0; nb < 4; nb++) {
            int dd0 = wn * 32 + nb * 8 + tig * 2;
            xb[(size_t)dd0 * (NH * NN) + r0]       = oc[mi][nb][0] * inv[2*mi];
            xb[(size_t)(dd0 + 1) * (NH * NN) + r0] = oc[mi][nb][1] * inv[2*mi];
            xb[(size_t)dd0 * (NH * NN) + r1]       = oc[mi][nb][2] * inv[2*mi+1];
            xb[(size_t)(dd0 + 1) * (NH * NN) + r1] = oc[mi][nb][3] * inv[2*mi+1];
        }
    }
}

// ---------------------------------------------------------------------------
extern "C" void kernel_launch(void* const* d_in, const int* in_sizes, int n_in,
                              void* d_out, int out_size)
{
    const float* query = (const float*)d_in[0];
    const float* key_  = (const float*)d_in[1];
    const float* value = (const float*)d_in[2];
    const int*   mask  = (const int*)  d_in[3];
    const float* Wq = (const float*)d_in[4];
    const float* bq = (const float*)d_in[5];
    const float* Wk = (const float*)d_in[6];
    const float* bk = (const float*)d_in[7];
    const float* Wv = (const float*)d_in[8];
    const float* bv = (const float*)d_in[9];
    const float* Wm = (const float*)d_in[10];
    const float* bm = (const float*)d_in[11];
    float* out = (float*)d_out;

    float *q, *k, *v, *x;
    cudaGetSymbolAddress((void**)&q, g_q);
    cudaGetSymbolAddress((void**)&k, g_k);
    cudaGetSymbolAddress((void**)&v, g_v);
    cudaGetSymbolAddress((void**)&x, g_x);

    const int psmem = 49152;  // A 32KB + B 16KB
    cudaFuncSetAttribute(proj_mma<1,1>, cudaFuncAttributeMaxDynamicSharedMemorySize, psmem);
    cudaFuncSetAttribute(proj_mma<1,0>, cudaFuncAttributeMaxDynamicSharedMemorySize, psmem);
    cudaFuncSetAttribute(proj_mma<0,0>, cudaFuncAttributeMaxDynamicSharedMemorySize, psmem);

    dim3 pmgrid(NN / 64, DD / 128, BB);
    proj_mma<1, 1><<<pmgrid, 256, psmem>>>(Wq, bq, query, q);  // q: tf32((Wq x + b)/8)
    proj_mma<1, 0><<<pmgrid, 256, psmem>>>(Wk, bk, key_,  k);  // k: tf32(Wk x + b)
    proj_mma<0, 0><<<pmgrid, 256, psmem>>>(Wv, bv, value, v);  // v: tf32(Wv x + b)

    const int asmem = 98304 + 64 * 4 + 2 * 128 * 4;  // 99584
    cudaFuncSetAttribute(attn_mma, cudaFuncAttributeMaxDynamicSharedMemorySize, asmem);
    dim3 agrid(NN / QTILE, NH, BB);
    attn_mma<<<agrid, 256, asmem>>>(mask);

    dim3 pgrid(NN / 128, DD / 64, BB);
    proj_kernel<<<pgrid, 256>>>(Wm, bm, x, out);
}

// round 11
// speedup vs baseline: 2.6172x; 1.0325x over previous
#include <cuda_runtime.h>
#include <math.h>
#include <stdint.h>

#define BB 8
#define DD 256
#define NN 2048
#define NH 4
#define HD 64
#define QTILE 128

typedef unsigned long long u64;
typedef unsigned int u32;

// Scratch. g_q/g_k TRANSPOSED per-head [b][h][tok][dd] (tf32 bits, q pre-scaled);
// g_v natural [b][ch][tok] (tf32 bits); g_x natural fp32.
__device__ float g_q[BB*DD*NN];
__device__ float g_k[BB*DD*NN];
__device__ float g_v[BB*DD*NN];
__device__ float g_x[BB*DD*NN];

__device__ __forceinline__ u32 f2tf32(float x) {
    u32 r; asm("cvt.rna.tf32.f32 %0, %1;" : "=r"(r) : "f"(x)); return r;
}
__device__ __forceinline__ u32 smem_u32(const void* p) {
    u32 a; asm("{ .reg .u64 t; cvta.to.shared.u64 t, %1; cvt.u32.u64 %0, t; }" : "=r"(a) : "l"(p));
    return a;
}
__device__ __forceinline__ void mma_tf32(float c[4], u32 a0, u32 a1, u32 a2, u32 a3,
                                         u32 b0, u32 b1) {
    asm volatile("mma.sync.aligned.m16n8k8.row.col.f32.tf32.tf32.f32 "
        "{%0,%1,%2,%3}, {%4,%5,%6,%7}, {%8,%9}, {%0,%1,%2,%3};"
        : "+f"(c[0]), "+f"(c[1]), "+f"(c[2]), "+f"(c[3])
        : "r"(a0), "r"(a1), "r"(a2), "r"(a3), "r"(b0), "r"(b1));
}
#define LDSM4(r, a) asm volatile( \
    "ldmatrix.sync.aligned.m8n8.x4.shared.b16 {%0,%1,%2,%3}, [%4];" \
    : "=r"((r)[0]), "=r"((r)[1]), "=r"((r)[2]), "=r"((r)[3]) : "r"(a))
#define STS2(a, x, y) asm volatile( \
    "st.shared.v2.b32 [%0], {%1,%2};" :: "r"(a), "r"(x), "r"(y) : "memory")
#define STS4(a, x, y, z, w_) asm volatile( \
    "st.shared.v4.b32 [%0], {%1,%2,%3,%4};" :: "r"(a), "r"(x), "r"(y), "r"(z), "r"(w_) : "memory")
#define CPA16(dst, src) asm volatile( \
    "cp.async.cg.shared.global [%0], [%1], 16;" :: "r"(dst), "l"(src) : "memory")
#define CPA_COMMIT() asm volatile("cp.async.commit_group;" ::: "memory")
#define CPA_WAIT0()  asm volatile("cp.async.wait_group 0;" ::: "memory")
#define CPA_WAIT1()  asm volatile("cp.async.wait_group 1;" ::: "memory")

// ---------------------------------------------------------------------------
// tf32 mma projection for q/k/v. C[o][tok] = W[o][i] · X^T[tok][i] + bias.
// CTA = (64-tok, 128-o, b), 256 thr, warps 4(m over o) x 2(n over tok).
// ---------------------------------------------------------------------------
template <int TRANSQ, int SCALE>
__global__ __launch_bounds__(256, 2) void proj_mma(
    const float* __restrict__ W, const float* __restrict__ bias,
    const float* __restrict__ X, float* __restrict__ Y)
{
    extern __shared__ u32 psm[];
    const u32 sbase = smem_u32(psm);
    const u32 Ao = 0;
    const u32 Bo = 32768;

    const int t = threadIdx.x;
    const int w = t >> 5, lane = t & 31;
    const int wm = w >> 1, wn = w & 1;
    const int gid = lane >> 2, tig = lane & 3;
    const int b  = blockIdx.z;
    const int o0 = blockIdx.y * 128;
    const int n0 = blockIdx.x * 64;

    const int arow0 = wm * 32 + (lane & 15);
    const int ahi = lane >> 4;
    const int brow8 = ((lane >> 4) << 3) + (lane & 7);
    const int bhi = (lane >> 3) & 1;

    const float* Xb = X + (size_t)b * DD * NN;

    float oc[2][4][4];
#pragma unroll
    for (int mi = 0; mi < 2; mi++)
#pragma unroll
        for (int nb = 0; nb < 4; nb++)
#pragma unroll
            for (int e = 0; e < 4; e++) oc[mi][nb][e] = 0.f;

    for (int kc = 0; kc < DD; kc += 64) {
        __syncthreads();
#pragma unroll
        for (int i = 0; i < 8; i++) {
            int idx = t + i * 256;
            int row = idx >> 4, c = idx & 15;
            float4 wv = *(const float4*)&W[(size_t)(o0 + row) * DD + kc + c * 4];
            u32 a = sbase + Ao + row * 256 + ((c ^ (row & 7)) << 4);
            STS4(a, f2tf32(wv.x), f2tf32(wv.y), f2tf32(wv.z), f2tf32(wv.w));
        }
#pragma unroll
        for (int i = 0; i < 4; i++) {
            int idx = t + i * 256;
            int tok = idx & 63, kq = idx >> 6;
            const float* src = Xb + (size_t)(kc + kq * 4) * NN + n0 + tok;
            u32 v0 = f2tf32(src[0]);
            u32 v1 = f2tf32(src[NN]);
            u32 v2 = f2tf32(src[2 * NN]);
            u32 v3 = f2tf32(src[3 * NN]);
            u32 a = sbase + Bo + tok * 256 + ((kq ^ (tok & 7)) << 4);
            STS4(a, v0, v1, v2, v3);
        }
        __syncthreads();

#pragma unroll
        for (int ks = 0; ks < 8; ks++) {
            u32 A0[4], A1[4];
            {
                int r = arow0;
                u32 a = sbase + Ao + r * 256 + (((ks * 2 + ahi) ^ (r & 7)) << 4);
                LDSM4(A0, a);
                r = arow0 + 16;
                a = sbase + Ao + r * 256 + (((ks * 2 + ahi) ^ (r & 7)) << 4);
                LDSM4(A1, a);
            }
#pragma unroll
            for (int nbp = 0; nbp < 2; nbp++) {
                int rr = wn * 32 + nbp * 16 + brow8;
                u32 ab = sbase + Bo + rr * 256 + (((ks * 2 + bhi) ^ (rr & 7)) << 4);
                u32 B[4]; LDSM4(B, ab);
                mma_tf32(oc[0][nbp*2],   A0[0], A0[1], A0[2], A0[3], B[0], B[1]);
                mma_tf32(oc[1][nbp*2],   A1[0], A1[1], A1[2], A1[3], B[0], B[1]);
                mma_tf32(oc[0][nbp*2+1], A0[0], A0[1], A0[2], A0[3], B[2], B[3]);
                mma_tf32(oc[1][nbp*2+1], A1[0], A1[1], A1[2], A1[3], B[2], B[3]);
            }
        }
    }

    float bv[2][2];
#pragma unroll
    for (int mi = 0; mi < 2; mi++) {
        bv[mi][0] = bias[o0 + wm * 32 + mi * 16 + gid];
        bv[mi][1] = bias[o0 + wm * 32 + mi * 16 + gid + 8];
    }
#pragma unroll
    for (int mi = 0; mi < 2; mi++)
#pragma unroll
    for (int nb = 0; nb < 4; nb++) {
        int token = n0 + wn * 32 + nb * 8 + tig * 2;
        float v0 = oc[mi][nb][0] + bv[mi][0];
        float v1 = oc[mi][nb][1] + bv[mi][0];
        float v2 = oc[mi][nb][2] + bv[mi][1];
        float v3 = oc[mi][nb][3] + bv[mi][1];
        if (SCALE) { v0 *= 0.125f; v1 *= 0.125f; v2 *= 0.125f; v3 *= 0.125f; }
        u32 t0 = f2tf32(v0), t1 = f2tf32(v1), t2 = f2tf32(v2), t3 = f2tf32(v3);
        int o = o0 + wm * 32 + mi * 16 + gid;
        if (TRANSQ) {
            {
                float* d = Y + (((size_t)b * NH + (o & 3)) * NN + token) * HD + (o >> 2);
                d[0]  = __uint_as_float(t0);
                d[HD] = __uint_as_float(t1);
            }
            {
                int o2 = o + 8;
                float* d = Y + (((size_t)b * NH + (o2 & 3)) * NN + token) * HD + (o2 >> 2);
                d[0]  = __uint_as_float(t2);
                d[HD] = __uint_as_float(t3);
            }
        } else {
            *(float2*)&Y[((size_t)b * DD + o) * NN + token] =
                make_float2(__uint_as_float(t0), __uint_as_float(t1));
            *(float2*)&Y[((size_t)b * DD + o + 8) * NN + token] =
                make_float2(__uint_as_float(t2), __uint_as_float(t3));
        }
    }
}

// ---------------------------------------------------------------------------
// 3xTF32 output projection (fp32-accurate): A = Wm hi/lo, B = x^T hi/lo.
// oc += Ahi·Bhi + Alo·Bhi + Ahi·Blo. Same geometry as proj_mma.
// ---------------------------------------------------------------------------
__global__ __launch_bounds__(256, 2) void proj_out3(
    const float* __restrict__ W, const float* __restrict__ bias,
    const float* __restrict__ X, float* __restrict__ Y)
{
    extern __shared__ u32 psm[];
    const u32 sbase = smem_u32(psm);
    const u32 Ahi = 0, Alo = 32768, Bhi = 65536, Blo = 81920;

    const int t = threadIdx.x;
    const int w = t >> 5, lane = t & 31;
    const int wm = w >> 1, wn = w & 1;
    const int gid = lane >> 2, tig = lane & 3;
    const int b  = blockIdx.z;
    const int o0 = blockIdx.y * 128;
    const int n0 = blockIdx.x * 64;

    const int arow0 = wm * 32 + (lane & 15);
    const int ahi = lane >> 4;
    const int brow8 = ((lane >> 4) << 3) + (lane & 7);
    const int bhi = (lane >> 3) & 1;

    const float* Xb = X + (size_t)b * DD * NN;

    float oc[2][4][4];
#pragma unroll
    for (int mi = 0; mi < 2; mi++)
#pragma unroll
        for (int nb = 0; nb < 4; nb++)
#pragma unroll
            for (int e = 0; e < 4; e++) oc[mi][nb][e] = 0.f;

    for (int kc = 0; kc < DD; kc += 64) {
        __syncthreads();
#pragma unroll
        for (int i = 0; i < 8; i++) {
            int idx = t + i * 256;
            int row = idx >> 4, c = idx & 15;
            float4 wv = *(const float4*)&W[(size_t)(o0 + row) * DD + kc + c * 4];
            u32 h0 = f2tf32(wv.x), h1 = f2tf32(wv.y), h2 = f2tf32(wv.z), h3 = f2tf32(wv.w);
            u32 l0 = f2tf32(wv.x - __uint_as_float(h0));
            u32 l1 = f2tf32(wv.y - __uint_as_float(h1));
            u32 l2 = f2tf32(wv.z - __uint_as_float(h2));
            u32 l3 = f2tf32(wv.w - __uint_as_float(h3));
            u32 off = row * 256 + ((c ^ (row & 7)) << 4);
            STS4(sbase + Ahi + off, h0, h1, h2, h3);
            STS4(sbase + Alo + off, l0, l1, l2, l3);
        }
#pragma unroll
        for (int i = 0; i < 4; i++) {
            int idx = t + i * 256;
            int tok = idx & 63, kq = idx >> 6;
            const float* src = Xb + (size_t)(kc + kq * 4) * NN + n0 + tok;
            float x0 = src[0], x1 = src[NN], x2 = src[2 * NN], x3 = src[3 * NN];
            u32 h0 = f2tf32(x0), h1 = f2tf32(x1), h2 = f2tf32(x2), h3 = f2tf32(x3);
            u32 l0 = f2tf32(x0 - __uint_as_float(h0));
            u32 l1 = f2tf32(x1 - __uint_as_float(h1));
            u32 l2 = f2tf32(x2 - __uint_as_float(h2));
            u32 l3 = f2tf32(x3 - __uint_as_float(h3));
            u32 off = tok * 256 + ((kq ^ (tok & 7)) << 4);
            STS4(sbase + Bhi + off, h0, h1, h2, h3);
            STS4(sbase + Blo + off, l0, l1, l2, l3);
        }
        __syncthreads();

        const u32 Ap[3] = {Ahi, Alo, Ahi};
        const u32 Bp[3] = {Bhi, Bhi, Blo};
#pragma unroll
        for (int pass = 0; pass < 3; pass++) {
#pragma unroll
            for (int ks = 0; ks < 8; ks++) {
                u32 A0[4], A1[4];
                {
                    int r = arow0;
                    u32 a = sbase + Ap[pass] + r * 256 + (((ks * 2 + ahi) ^ (r & 7)) << 4);
                    LDSM4(A0, a);
                    r = arow0 + 16;
                    a = sbase + Ap[pass] + r * 256 + (((ks * 2 + ahi) ^ (r & 7)) << 4);
                    LDSM4(A1, a);
                }
#pragma unroll
                for (int nbp = 0; nbp < 2; nbp++) {
                    int rr = wn * 32 + nbp * 16 + brow8;
                    u32 ab = sbase + Bp[pass] + rr * 256 + (((ks * 2 + bhi) ^ (rr & 7)) << 4);
                    u32 B[4]; LDSM4(B, ab);
                    mma_tf32(oc[0][nbp*2],   A0[0], A0[1], A0[2], A0[3], B[0], B[1]);
                    mma_tf32(oc[1][nbp*2],   A1[0], A1[1], A1[2], A1[3], B[0], B[1]);
                    mma_tf32(oc[0][nbp*2+1], A0[0], A0[1], A0[2], A0[3], B[2], B[3]);
                    mma_tf32(oc[1][nbp*2+1], A1[0], A1[1], A1[2], A1[3], B[2], B[3]);
                }
            }
        }
    }

    float bv[2][2];
#pragma unroll
    for (int mi = 0; mi < 2; mi++) {
        bv[mi][0] = bias[o0 + wm * 32 + mi * 16 + gid];
        bv[mi][1] = bias[o0 + wm * 32 + mi * 16 + gid + 8];
    }
#pragma unroll
    for (int mi = 0; mi < 2; mi++)
#pragma unroll
    for (int nb = 0; nb < 4; nb++) {
        int token = n0 + wn * 32 + nb * 8 + tig * 2;
        int o = o0 + wm * 32 + mi * 16 + gid;
        *(float2*)&Y[((size_t)b * DD + o) * NN + token] =
            make_float2(oc[mi][nb][0] + bv[mi][0], oc[mi][nb][1] + bv[mi][0]);
        *(float2*)&Y[((size_t)b * DD + o + 8) * NN + token] =
            make_float2(oc[mi][nb][2] + bv[mi][1], oc[mi][nb][3] + bv[mi][1]);
    }
}

// ---------------------------------------------------------------------------
// mma.sync tf32 flash attention, double-buffered cp.async pipeline, KTILE=32.
// CTA = (b, h, 128-q tile), 256 threads, warps 4(m) x 2(n: 16 cols of S).
// SMEM bytes: Q[128x64]@0, K2[32x64]@32768/40960, V2[64x32]@49152/57344,
//             P[128x32]@65536, maskf[2048]@81920, sL@90112.
// ---------------------------------------------------------------------------
__global__ __launch_bounds__(256, 2) void attn_mma(const int* __restrict__ mask)
{
    extern __shared__ u32 smu[];
    const u32 sbase = smem_u32(smu);
    const u32 Qo = 0;
    const u32 Kob[2] = {32768u, 40960u};
    const u32 Vob[2] = {49152u, 57344u};
    const u32 Po = 65536;
    float* sMask = (float*)(smu + 20480);
    float* sL = (float*)(smu + 22528);

    const int t = threadIdx.x;
    const int w = t >> 5, lane = t & 31;
    const int wm = w >> 1, wn = w & 1;
    const int gid = lane >> 2, tig = lane & 3;
    const int b = blockIdx.z, h = blockIdx.y;
    const int q0 = blockIdx.x * QTILE;

    const int arow0 = wm * 32 + (lane & 15);
    const int ahi = lane >> 4;
    const int brow8 = ((lane >> 4) << 3) + (lane & 7);
    const int bhi = (lane >> 3) & 1;

    const float* qb = g_q + (((size_t)b * NH + h) * NN + q0) * HD;
    const float* kb0 = g_k + (((size_t)b * NH + h) * NN) * HD;
    const float* vb0 = g_v + ((size_t)b * DD + h) * NN;
    const int* mb_ = mask + (size_t)b * NN;

    // ---- prologue: Q fill + mask fill + tile0 fill, one commit group ----
#pragma unroll
    for (int i = 0; i < 2; i++) {
        int idx = t + i * 256;
        int row = idx >> 2, c4 = (idx & 3) * 4;
#pragma unroll
        for (int j = 0; j < 4; j++) {
            int c = c4 + j;
            u32 a = sbase + Qo + row * 256 + ((c ^ (row & 7)) << 4);
            CPA16(a, qb + row * HD + c * 4);
        }
    }
#pragma unroll
    for (int i = 0; i < 8; i++) {
        int j = t + i * 256;
        sMask[j] = (float)mb_[j];
    }
    // tile 0 -> buffers 0
#pragma unroll
    for (int i = 0; i < 2; i++) {
        int idx = t + i * 256;
        int row = idx >> 4, c = idx & 15;       // K: 32 rows x 16 chunks
        u32 a = sbase + Kob[0] + row * 256 + ((c ^ (row & 7)) << 4);
        CPA16(a, kb0 + (size_t)row * HD + c * 4);
    }
#pragma unroll
    for (int i = 0; i < 2; i++) {
        int idx = t + i * 256;
        int dd = idx >> 3, c = idx & 7;         // V: 64 rows x 8 chunks
        u32 a = sbase + Vob[0] + dd * 128 + ((c ^ (dd & 7)) << 4);
        CPA16(a, vb0 + (size_t)dd * (NH * NN) + c * 4);
    }
    CPA_COMMIT();

    float qmf[4];
    qmf[0] = (float)mb_[q0 + wm * 32 + gid];
    qmf[1] = (float)mb_[q0 + wm * 32 + gid + 8];
    qmf[2] = (float)mb_[q0 + wm * 32 + gid + 16];
    qmf[3] = (float)mb_[q0 + wm * 32 + gid + 24];

    float oc[2][4][4];
#pragma unroll
    for (int mi = 0; mi < 2; mi++)
#pragma unroll
        for (int nb = 0; nb < 4; nb++)
#pragma unroll
            for (int e = 0; e < 4; e++) oc[mi][nb][e] = 0.f;
    float lsum[4] = {0.f, 0.f, 0.f, 0.f};

    for (int it = 0; it < 64; it++) {
        const int k0 = it * 32;
        const int cur = it & 1;
        __syncthreads();   // closes prev-iter PV reads of the buffer we refill
        if (it + 1 < 64) {
            const int nxt = 1 - cur;
            const int k0n = k0 + 32;
#pragma unroll
            for (int i = 0; i < 2; i++) {
                int idx = t + i * 256;
                int row = idx >> 4, c = idx & 15;
                u32 a = sbase + Kob[nxt] + row * 256 + ((c ^ (row & 7)) << 4);
                CPA16(a, kb0 + (size_t)(k0n + row) * HD + c * 4);
            }
#pragma unroll
            for (int i = 0; i < 2; i++) {
                int idx = t + i * 256;
                int dd = idx >> 3, c = idx & 7;
                u32 a = sbase + Vob[nxt] + dd * 128 + ((c ^ (dd & 7)) << 4);
                CPA16(a, vb0 + (size_t)dd * (NH * NN) + k0n + c * 4);
            }
            CPA_COMMIT();
            CPA_WAIT1();
        } else {
            CPA_WAIT0();
        }
        __syncthreads();   // tile `it` visible to all warps

        // ---- S = Q K^T (warp: 32 q x 16 k) ----
        float sc[2][2][4];
#pragma unroll
        for (int mi = 0; mi < 2; mi++)
#pragma unroll
            for (int nb = 0; nb < 2; nb++)
#pragma unroll
                for (int e = 0; e < 4; e++) sc[mi][nb][e] = 0.f;
#pragma unroll
        for (int ks = 0; ks < 8; ks++) {
            u32 A0[4], A1[4];
            {
                int r = arow0;
                u32 a = sbase + Qo + r * 256 + (((ks * 2 + ahi) ^ (r & 7)) << 4);
                LDSM4(A0, a);
                r = arow0 + 16;
                a = sbase + Qo + r * 256 + (((ks * 2 + ahi) ^ (r & 7)) << 4);
                LDSM4(A1, a);
            }
            int rr = wn * 16 + brow8;
            u32 ab = sbase + Kob[cur] + rr * 256 + (((ks * 2 + bhi) ^ (rr & 7)) << 4);
            u32 B[4]; LDSM4(B, ab);
            mma_tf32(sc[0][0], A0[0], A0[1], A0[2], A0[3], B[0], B[1]);
            mma_tf32(sc[1][0], A1[0], A1[1], A1[2], A1[3], B[0], B[1]);
            mma_tf32(sc[0][1], A0[0], A0[1], A0[2], A0[3], B[2], B[3]);
            mma_tf32(sc[1][1], A1[0], A1[1], A1[2], A1[3], B[2], B[3]);
        }

        // ---- softmax (no-max, multiply-mask), P -> sP ----
#pragma unroll
        for (int nb = 0; nb < 2; nb++) {
            int col0 = wn * 16 + nb * 8 + tig * 2;
            float km0 = sMask[k0 + col0], km1 = sMask[k0 + col0 + 1];
            float e0 = __expf(sc[0][nb][0]) * qmf[0] * km0;
            float e1 = __expf(sc[0][nb][1]) * qmf[0] * km1;
            float e2 = __expf(sc[0][nb][2]) * qmf[1] * km0;
            float e3 = __expf(sc[0][nb][3]) * qmf[1] * km1;
            float f0 = __expf(sc[1][nb][0]) * qmf[2] * km0;
            float f1 = __expf(sc[1][nb][1]) * qmf[2] * km1;
            float f2 = __expf(sc[1][nb][2]) * qmf[3] * km0;
            float f3 = __expf(sc[1][nb][3]) * qmf[3] * km1;
            lsum[0] += e0 + e1; lsum[1] += e2 + e3;
            lsum[2] += f0 + f1; lsum[3] += f2 + f3;
            int ch = col0 >> 2;   // 0..7
            int r0 = wm * 32 + gid;
            u32 a0 = sbase + Po + r0 * 128 + ((ch ^ (r0 & 7)) << 4) + (tig & 1) * 8;
            STS2(a0, f2tf32(e0), f2tf32(e1));
            int r1 = r0 + 8;
            u32 a1 = sbase + Po + r1 * 128 + ((ch ^ (r1 & 7)) << 4) + (tig & 1) * 8;
            STS2(a1, f2tf32(e2), f2tf32(e3));
            int r2 = r0 + 16;
            u32 a2 = sbase + Po + r2 * 128 + ((ch ^ (r2 & 7)) << 4) + (tig & 1) * 8;
            STS2(a2, f2tf32(f0), f2tf32(f1));
            int r3 = r0 + 24;
            u32 a3 = sbase + Po + r3 * 128 + ((ch ^ (r3 & 7)) << 4) + (tig & 1) * 8;
            STS2(a3, f2tf32(f2), f2tf32(f3));
        }
        __syncthreads();   // P visible to both n-warps

        // ---- O += P V (kt 0..3 over 32 tokens) ----
#pragma unroll
        for (int kt = 0; kt < 4; kt++) {
            u32 A0[4], A1[4];
            {
                int r = arow0;
                u32 a = sbase + Po + r * 128 + (((kt * 2 + ahi) ^ (r & 7)) << 4);
                LDSM4(A0, a);
                r = arow0 + 16;
                a = sbase + Po + r * 128 + (((kt * 2 + ahi) ^ (r & 7)) << 4);
                LDSM4(A1, a);
            }
#pragma unroll
            for (int nbp = 0; nbp < 2; nbp++) {
                int rr = wn * 32 + nbp * 16 + brow8;
                u32 ab = sbase + Vob[cur] + rr * 128 + (((kt * 2 + bhi) ^ (rr & 7)) << 4);
                u32 B[4]; LDSM4(B, ab);
                mma_tf32(oc[0][nbp*2],   A0[0], A0[1], A0[2], A0[3], B[0], B[1]);
                mma_tf32(oc[1][nbp*2],   A1[0], A1[1], A1[2], A1[3], B[0], B[1]);
                mma_tf32(oc[0][nbp*2+1], A0[0], A0[1], A0[2], A0[3], B[2], B[3]);
                mma_tf32(oc[1][nbp*2+1], A1[0], A1[1], A1[2], A1[3], B[2], B[3]);
            }
        }
    }

    // ---- reduce l, epilogue ----
#pragma unroll
    for (int i = 0; i < 4; i++) {
        lsum[i] += __shfl_xor_sync(~0u, lsum[i], 1);
        lsum[i] += __shfl_xor_sync(~0u, lsum[i], 2);
    }
    if (tig == 0) {
        sL[wn * 128 + wm * 32 + gid]      = lsum[0];
        sL[wn * 128 + wm * 32 + gid + 8]  = lsum[1];
        sL[wn * 128 + wm * 32 + gid + 16] = lsum[2];
        sL[wn * 128 + wm * 32 + gid + 24] = lsum[3];
    }
    __syncthreads();
    float inv[4];
#pragma unroll
    for (int i = 0; i < 4; i++) {
        int rl = wm * 32 + ((i & 1) ? 8 : 0) + ((i >> 1) ? 16 : 0) + gid;
        inv[i] = 1.f / (sL[rl] + sL[128 + rl]);
    }

    float* xb = g_x + ((size_t)b * DD + h) * NN;
#pragma unroll
    for (int mi = 0; mi < 2; mi++) {
        int r0 = q0 + wm * 32 + mi * 16 + gid;
        int r1 = r0 + 8;
#pragma unroll
        for (int nb = 0; nb < 4; nb++) {
            int dd0 = wn * 32 + nb * 8 + tig * 2;
            xb[(size_t)dd0 * (NH * NN) + r0]       = oc[mi][nb][0] * inv[2*mi];
            xb[(size_t)(dd0 + 1) * (NH * NN) + r0] = oc[mi][nb][1] * inv[2*mi];
            xb[(size_t)dd0 * (NH * NN) + r1]       = oc[mi][nb][2] * inv[2*mi+1];
            xb[(size_t)(dd0 + 1) * (NH * NN) + r1] = oc[mi][nb][3] * inv[2*mi+1];
        }
    }
}

// ---------------------------------------------------------------------------
extern "C" void kernel_launch(void* const* d_in, const int* in_sizes, int n_in,
                              void* d_out, int out_size)
{
    const float* query = (const float*)d_in[0];
    const float* key_  = (const float*)d_in[1];
    const float* value = (const float*)d_in[2];
    const int*   mask  = (const int*)  d_in[3];
    const float* Wq = (const float*)d_in[4];
    const float* bq = (const float*)d_in[5];
    const float* Wk = (const float*)d_in[6];
    const float* bk = (const float*)d_in[7];
    const float* Wv = (const float*)d_in[8];
    const float* bv = (const float*)d_in[9];
    const float* Wm = (const float*)d_in[10];
    const float* bm = (const float*)d_in[11];
    float* out = (float*)d_out;

    float *q, *k, *v, *x;
    cudaGetSymbolAddress((void**)&q, g_q);
    cudaGetSymbolAddress((void**)&k, g_k);
    cudaGetSymbolAddress((void**)&v, g_v);
    cudaGetSymbolAddress((void**)&x, g_x);

    const int psmem = 49152;
    cudaFuncSetAttribute(proj_mma<1,1>, cudaFuncAttributeMaxDynamicSharedMemorySize, psmem);
    cudaFuncSetAttribute(proj_mma<1,0>, cudaFuncAttributeMaxDynamicSharedMemorySize, psmem);
    cudaFuncSetAttribute(proj_mma<0,0>, cudaFuncAttributeMaxDynamicSharedMemorySize, psmem);

    dim3 pmgrid(NN / 64, DD / 128, BB);
    proj_mma<1, 1><<<pmgrid, 256, psmem>>>(Wq, bq, query, q);
    proj_mma<1, 0><<<pmgrid, 256, psmem>>>(Wk, bk, key_,  k);
    proj_mma<0, 0><<<pmgrid, 256, psmem>>>(Wv, bv, value, v);

    const int asmem = 91136 + 1024;  // tiles + mask + sL slack
    cudaFuncSetAttribute(attn_mma, cudaFuncAttributeMaxDynamicSharedMemorySize, asmem);
    dim3 agrid(NN / QTILE, NH, BB);
    attn_mma<<<agrid, 256, asmem>>>(mask);

    const int osmem = 98304;
    cudaFuncSetAttribute(proj_out3, cudaFuncAttributeMaxDynamicSharedMemorySize, osmem);
    proj_out3<<<pmgrid, 256, osmem>>>(Wm, bm, x, out);
}